// round 2
// baseline (speedup 1.0000x reference)
#include <cuda_runtime.h>
#include <math.h>

// Problem constants
#define NSP   8192          // D*H*W = 8*32*32
#define CIN   256
#define K27   27
#define CK    6912          // CIN * 27
#define DD    8
#define HH    32
#define WW    32

// Scratch (allocation-free rule: __device__ globals)
__device__ float g_S[CK * NSP];        // im2col / sampled matrix [c*27+k][p]  (~226.5 MB)
__device__ float g_d[108 * NSP];       // offset-conv output (108 channels)
__device__ float g_h[2][CIN * NSP];    // hidden ping-pong

// ---------------------------------------------------------------------------
// im2col for the plain 3x3x3 pad-1 conv: S[(c*27+k)][p] = x[c, p + tap_k] (0 pad)
// ---------------------------------------------------------------------------
__global__ void im2col_kernel(const float* __restrict__ src, float* __restrict__ S) {
    int p = blockIdx.x * 256 + threadIdx.x;   // grid.x = 32
    int k = blockIdx.y;                        // 27
    int c = blockIdx.z;                        // 256
    int z = p >> 10, y = (p >> 5) & 31, x = p & 31;
    int kd = k / 9, kh = (k / 3) % 3, kw = k % 3;
    int zz = z + kd - 1, yy = y + kh - 1, xx = x + kw - 1;
    float v = 0.0f;
    if ((unsigned)zz < DD && (unsigned)yy < HH && (unsigned)xx < WW)
        v = src[c * NSP + (zz << 10) + (yy << 5) + xx];
    S[(c * K27 + k) * NSP + p] = v;
}

// ---------------------------------------------------------------------------
// Deformable sampling: for each (k,p) compute trilinear corner weights once
// (incl. validity mask and sigmoid modulation), then sweep channels.
// S[(c*27+k)][p] = mask(k,p) * trilinear(src[c], coord(k,p))
// ---------------------------------------------------------------------------
__global__ void sample_kernel(const float* __restrict__ src,
                              const float* __restrict__ dd,
                              float* __restrict__ S) {
    int p = blockIdx.x * 128 + threadIdx.x;   // grid.x = 64
    int k = blockIdx.y;                        // 27
    int z = p >> 10, y = (p >> 5) & 31, x = p & 31;
    int kd = k / 9, kh = (k / 3) % 3, kw = k % 3;

    float cd = (float)(z + kd - 1) + dd[(k * 3 + 0) * NSP + p];
    float ch = (float)(y + kh - 1) + dd[(k * 3 + 1) * NSP + p];
    float cw = (float)(x + kw - 1) + dd[(k * 3 + 2) * NSP + p];
    float m  = 1.0f / (1.0f + expf(-dd[(81 + k) * NSP + p]));

    float d0 = floorf(cd), h0 = floorf(ch), w0 = floorf(cw);
    float fd = cd - d0, fh = ch - h0, fw = cw - w0;
    int z0 = (int)d0, y0 = (int)h0, x0 = (int)w0;

    float wt[8]; int idx[8];
#pragma unroll
    for (int j = 0; j < 8; j++) {
        int dz = (j >> 2) & 1, dy = (j >> 1) & 1, dx = j & 1;
        int zi = z0 + dz, yi = y0 + dy, xi = x0 + dx;
        float w = (dz ? fd : 1.0f - fd) * (dy ? fh : 1.0f - fh) * (dx ? fw : 1.0f - fw);
        bool valid = ((unsigned)zi < DD) && ((unsigned)yi < HH) && ((unsigned)xi < WW);
        wt[j] = valid ? (w * m) : 0.0f;
        int zc = min(max(zi, 0), DD - 1);
        int yc = min(max(yi, 0), HH - 1);
        int xc = min(max(xi, 0), WW - 1);
        idx[j] = (zc << 10) + (yc << 5) + xc;
    }

    float* out = S + (size_t)k * NSP + p;
#pragma unroll 4
    for (int c = 0; c < CIN; c++) {
        const float* b = src + c * NSP;
        float acc = wt[0] * b[idx[0]] + wt[1] * b[idx[1]]
                  + wt[2] * b[idx[2]] + wt[3] * b[idx[3]]
                  + wt[4] * b[idx[4]] + wt[5] * b[idx[5]]
                  + wt[6] * b[idx[6]] + wt[7] * b[idx[7]];
        out[(size_t)c * K27 * NSP] = acc;
    }
}

// ---------------------------------------------------------------------------
// SGEMM: C[M][8192] = A[M][6912] * B[6912][8192] + bias, optional ReLU.
// BM=64, BN=128, BK=16, 256 threads, 4x8 per-thread tile, FFMA2 (f32x2) core,
// register double buffering of the gmem->smem pipeline.
// ---------------------------------------------------------------------------
#define BM 64
#define BN 128
#define BK 16

__global__ __launch_bounds__(256) void sgemm_kernel(
    const float* __restrict__ A, const float* __restrict__ B,
    const float* __restrict__ bias, float* __restrict__ C,
    int M, int doRelu)
{
    __shared__ float As[BK][BM];
    __shared__ float Bs[BK][BN];

    int tid = threadIdx.x;
    int bm = blockIdx.y, bn = blockIdx.x;

    // A tile loader: one float4 per thread (64 rows x 16 cols)
    int ar = tid >> 2;               // 0..63
    int ac = (tid & 3) << 2;         // 0,4,8,12
    int aRow = bm * BM + ar;
    const float* Aptr = A + (size_t)aRow * CK + ac;

    // B tile loader: two float4 per thread (16 rows x 128 cols)
    int br0 = tid >> 5;              // 0..7
    int bc0 = (tid & 31) << 2;       // 0..124
    const float* Bptr = B + (size_t)bn * BN;

    // compute mapping
    int m0 = (tid >> 4) << 2;        // 0..60
    int c0 = (tid & 15) << 2;        // 0..60 (cols c0..c0+3 and c0+64..c0+67)

    float4 aReg, bReg0, bReg1;
    if (aRow < M) aReg = *(const float4*)(Aptr);
    else          aReg = make_float4(0.f, 0.f, 0.f, 0.f);
    bReg0 = *(const float4*)(Bptr + (size_t)br0 * NSP + bc0);
    bReg1 = *(const float4*)(Bptr + (size_t)(br0 + 8) * NSP + bc0);

    unsigned long long acc[16];
#pragma unroll
    for (int i = 0; i < 16; i++) acc[i] = 0ull;

    const int KT = CK / BK;  // 432
    for (int kt = 0; kt < KT; kt++) {
        As[ac + 0][ar] = aReg.x;
        As[ac + 1][ar] = aReg.y;
        As[ac + 2][ar] = aReg.z;
        As[ac + 3][ar] = aReg.w;
        *(float4*)&Bs[br0][bc0]     = bReg0;
        *(float4*)&Bs[br0 + 8][bc0] = bReg1;
        __syncthreads();

        if (kt + 1 < KT) {
            const float* An = Aptr + (size_t)(kt + 1) * BK;
            if (aRow < M) aReg = *(const float4*)(An);
            else          aReg = make_float4(0.f, 0.f, 0.f, 0.f);
            const float* Bn = Bptr + (size_t)(kt + 1) * BK * NSP;
            bReg0 = *(const float4*)(Bn + (size_t)br0 * NSP + bc0);
            bReg1 = *(const float4*)(Bn + (size_t)(br0 + 8) * NSP + bc0);
        }

#pragma unroll
        for (int kk = 0; kk < BK; kk++) {
            float4 a4 = *(const float4*)&As[kk][m0];
            const unsigned long long* b2a = (const unsigned long long*)&Bs[kk][c0];
            const unsigned long long* b2b = (const unsigned long long*)&Bs[kk][c0 + 64];
            unsigned long long bp[4] = { b2a[0], b2a[1], b2b[0], b2b[1] };
            float am[4] = { a4.x, a4.y, a4.z, a4.w };
#pragma unroll
            for (int i = 0; i < 4; i++) {
                unsigned long long ap;
                asm("mov.b64 %0, {%1, %1};" : "=l"(ap) : "f"(am[i]));
#pragma unroll
                for (int j = 0; j < 4; j++) {
                    asm("fma.rn.f32x2 %0, %1, %2, %0;"
                        : "+l"(acc[i * 4 + j]) : "l"(ap), "l"(bp[j]));
                }
            }
        }
        __syncthreads();
    }

    // epilogue: bias (+ReLU) and store
#pragma unroll
    for (int i = 0; i < 4; i++) {
        int mg = bm * BM + m0 + i;
        if (mg >= M) break;
        float bv = bias[mg];
        float lo[4], hi[4];
#pragma unroll
        for (int j = 0; j < 4; j++) {
            asm("mov.b64 {%0, %1}, %2;" : "=f"(lo[j]), "=f"(hi[j]) : "l"(acc[i * 4 + j]));
            lo[j] += bv; hi[j] += bv;
            if (doRelu) { lo[j] = fmaxf(lo[j], 0.f); hi[j] = fmaxf(hi[j], 0.f); }
        }
        float* Cp = C + (size_t)mg * NSP + bn * BN;
        *(float4*)(Cp + c0)      = make_float4(lo[0], hi[0], lo[1], hi[1]);
        *(float4*)(Cp + c0 + 64) = make_float4(lo[2], hi[2], lo[3], hi[3]);
    }
}

// ---------------------------------------------------------------------------
// Driver
// ---------------------------------------------------------------------------
extern "C" void kernel_launch(void* const* d_in, const int* in_sizes, int n_in,
                              void* d_out, int out_size) {
    (void)in_sizes; (void)n_in; (void)out_size;
    const float* x = (const float*)d_in[0];
    const float* ow[4] = { (const float*)d_in[1], (const float*)d_in[5],
                           (const float*)d_in[9], (const float*)d_in[13] };
    const float* ob[4] = { (const float*)d_in[2], (const float*)d_in[6],
                           (const float*)d_in[10], (const float*)d_in[14] };
    const float* w[4]  = { (const float*)d_in[3], (const float*)d_in[7],
                           (const float*)d_in[11], (const float*)d_in[15] };
    const float* b[4]  = { (const float*)d_in[4], (const float*)d_in[8],
                           (const float*)d_in[12], (const float*)d_in[16] };
    float* out = (float*)d_out;

    float *S, *dbuf, *hbuf;
    cudaGetSymbolAddress((void**)&S,    g_S);
    cudaGetSymbolAddress((void**)&dbuf, g_d);
    cudaGetSymbolAddress((void**)&hbuf, g_h);
    float* h0 = hbuf;
    float* h1 = hbuf + (size_t)CIN * NSP;

    dim3 im2colGrid(NSP / 256, K27, CIN);
    dim3 sampleGrid(NSP / 128, K27);
    dim3 gemmGridOff(NSP / BN, (108 + BM - 1) / BM);  // 64 x 2
    dim3 gemmGridMain(NSP / BN, CIN / BM);            // 64 x 4

    const float* in = x;
    // three mdconv3d layers (ReLU)
    for (int L = 0; L < 3; L++) {
        im2col_kernel<<<im2colGrid, 256>>>(in, S);
        sgemm_kernel<<<gemmGridOff, 256>>>(ow[L], S, ob[L], dbuf, 108, 0);
        sample_kernel<<<sampleGrid, 128>>>(in, dbuf, S);
        float* hn = (L & 1) ? h1 : h0;
        sgemm_kernel<<<gemmGridMain, 256>>>(w[L], S, b[L], hn, CIN, 1);
        in = hn;
    }
    // final: offsets from conv(h3), deformable conv applied to ORIGINAL x, no ReLU
    im2col_kernel<<<im2colGrid, 256>>>(in, S);
    sgemm_kernel<<<gemmGridOff, 256>>>(ow[3], S, ob[3], dbuf, 108, 0);
    sample_kernel<<<sampleGrid, 128>>>(x, dbuf, S);
    sgemm_kernel<<<gemmGridMain, 256>>>(w[3], S, b[3], out, CIN, 0);
}

// round 5
// speedup vs baseline: 1.0660x; 1.0660x over previous
#include <cuda_runtime.h>
#include <math.h>

// Problem constants
#define NSP   8192          // D*H*W = 8*32*32
#define CIN   256
#define K27   27
#define CK    6912          // CIN * 27
#define DD    8
#define HH    32
#define WW    32

typedef unsigned long long ull;

// Scratch (allocation-free rule: __device__ globals)
__device__ float g_S[CK * NSP];        // sampled matrix [c*27+k][p]  (~226.5 MB)
__device__ float g_d[108 * NSP];       // offset-conv output (108 channels)
__device__ float g_h[2][CIN * NSP];    // hidden ping-pong

// ---------------------------------------------------------------------------
// Deformable sampling: per (k,p) compute trilinear corner weights once
// (incl. validity mask and sigmoid modulation), then sweep channels.
// ---------------------------------------------------------------------------
__global__ void sample_kernel(const float* __restrict__ src,
                              const float* __restrict__ dd,
                              float* __restrict__ S) {
    int p = blockIdx.x * 128 + threadIdx.x;   // grid.x = 64
    int k = blockIdx.y;                        // 27
    int z = p >> 10, y = (p >> 5) & 31, x = p & 31;
    int kd = k / 9, kh = (k / 3) % 3, kw = k % 3;

    float cd = (float)(z + kd - 1) + dd[(k * 3 + 0) * NSP + p];
    float ch = (float)(y + kh - 1) + dd[(k * 3 + 1) * NSP + p];
    float cw = (float)(x + kw - 1) + dd[(k * 3 + 2) * NSP + p];
    float m  = 1.0f / (1.0f + expf(-dd[(81 + k) * NSP + p]));

    float d0 = floorf(cd), h0 = floorf(ch), w0 = floorf(cw);
    float fd = cd - d0, fh = ch - h0, fw = cw - w0;
    int z0 = (int)d0, y0 = (int)h0, x0 = (int)w0;

    float wt[8]; int idx[8];
#pragma unroll
    for (int j = 0; j < 8; j++) {
        int dz = (j >> 2) & 1, dy = (j >> 1) & 1, dx = j & 1;
        int zi = z0 + dz, yi = y0 + dy, xi = x0 + dx;
        float w = (dz ? fd : 1.0f - fd) * (dy ? fh : 1.0f - fh) * (dx ? fw : 1.0f - fw);
        bool valid = ((unsigned)zi < DD) && ((unsigned)yi < HH) && ((unsigned)xi < WW);
        wt[j] = valid ? (w * m) : 0.0f;
        int zc = min(max(zi, 0), DD - 1);
        int yc = min(max(yi, 0), HH - 1);
        int xc = min(max(xi, 0), WW - 1);
        idx[j] = (zc << 10) + (yc << 5) + xc;
    }

    float* out = S + (size_t)k * NSP + p;
#pragma unroll 4
    for (int c = 0; c < CIN; c++) {
        const float* b = src + c * NSP;
        float acc = wt[0] * b[idx[0]] + wt[1] * b[idx[1]]
                  + wt[2] * b[idx[2]] + wt[3] * b[idx[3]]
                  + wt[4] * b[idx[4]] + wt[5] * b[idx[5]]
                  + wt[6] * b[idx[6]] + wt[7] * b[idx[7]];
        out[(size_t)c * K27 * NSP] = acc;
    }
}

// ---------------------------------------------------------------------------
// Main SGEMM: C[M][8192] = A[M][6912] * S[6912][8192] + bias (+ReLU).
// BM=128, BN=128, BK=16, 256 threads, 8x8 per-thread tile, f32x2 FFMA core.
// ---------------------------------------------------------------------------
#define BM 128
#define BN 128
#define BK 16

__global__ __launch_bounds__(256) void sgemm128(
    const float* __restrict__ A, const float* __restrict__ B,
    const float* __restrict__ bias, float* __restrict__ C,
    int M, int doRelu)
{
    __shared__ float As[BK][BM];
    __shared__ float Bs[BK][BN];

    int tid = threadIdx.x;
    int bm = blockIdx.y, bn = blockIdx.x;

    // A loader: rows ar0 and ar0+64, 4 cols at ac  (128x16 tile, 2 float4/thread)
    int ar0 = tid >> 2;               // 0..63
    int ac  = (tid & 3) << 2;         // 0,4,8,12
    int aRow0 = bm * BM + ar0;
    int aRow1 = aRow0 + 64;
    const float* Ap0 = A + (size_t)aRow0 * CK + ac;
    const float* Ap1 = A + (size_t)aRow1 * CK + ac;

    // B loader: rows br, br+8, cols bc..bc+3 (16x128 tile, 2 float4/thread)
    int br = tid >> 5;                // 0..7
    int bc = (tid & 31) << 2;         // 0..124
    const float* Bp = B + (size_t)bn * BN;

    // compute mapping: 16x16 thread grid, 8x8 tile each
    int m0 = (tid >> 4) << 3;
    int n0 = (tid & 15) << 3;

    float4 aR0, aR1, bR0, bR1;
    aR0 = (aRow0 < M) ? *(const float4*)Ap0 : make_float4(0.f,0.f,0.f,0.f);
    aR1 = (aRow1 < M) ? *(const float4*)Ap1 : make_float4(0.f,0.f,0.f,0.f);
    bR0 = *(const float4*)(Bp + (size_t)br * NSP + bc);
    bR1 = *(const float4*)(Bp + (size_t)(br + 8) * NSP + bc);

    ull acc[32];
#pragma unroll
    for (int i = 0; i < 32; i++) acc[i] = 0ull;

    const int KT = CK / BK;  // 432
    for (int kt = 0; kt < KT; kt++) {
        As[ac + 0][ar0] = aR0.x; As[ac + 1][ar0] = aR0.y;
        As[ac + 2][ar0] = aR0.z; As[ac + 3][ar0] = aR0.w;
        As[ac + 0][ar0 + 64] = aR1.x; As[ac + 1][ar0 + 64] = aR1.y;
        As[ac + 2][ar0 + 64] = aR1.z; As[ac + 3][ar0 + 64] = aR1.w;
        *(float4*)&Bs[br][bc]     = bR0;
        *(float4*)&Bs[br + 8][bc] = bR1;
        __syncthreads();

        if (kt + 1 < KT) {
            size_t ka = (size_t)(kt + 1) * BK;
            aR0 = (aRow0 < M) ? *(const float4*)(Ap0 + ka) : make_float4(0.f,0.f,0.f,0.f);
            aR1 = (aRow1 < M) ? *(const float4*)(Ap1 + ka) : make_float4(0.f,0.f,0.f,0.f);
            const float* Bn = Bp + (size_t)(kt + 1) * BK * NSP;
            bR0 = *(const float4*)(Bn + (size_t)br * NSP + bc);
            bR1 = *(const float4*)(Bn + (size_t)(br + 8) * NSP + bc);
        }

#pragma unroll
        for (int kk = 0; kk < BK; kk++) {
            float4 a0 = *(const float4*)&As[kk][m0];
            float4 a1 = *(const float4*)&As[kk][m0 + 4];
            const ull* bp = (const ull*)&Bs[kk][n0];
            ull b[4] = { bp[0], bp[1], bp[2], bp[3] };
            float am[8] = { a0.x, a0.y, a0.z, a0.w, a1.x, a1.y, a1.z, a1.w };
#pragma unroll
            for (int i = 0; i < 8; i++) {
                ull ap;
                asm("mov.b64 %0, {%1, %1};" : "=l"(ap) : "f"(am[i]));
#pragma unroll
                for (int j = 0; j < 4; j++) {
                    asm("fma.rn.f32x2 %0, %1, %2, %0;"
                        : "+l"(acc[i * 4 + j]) : "l"(ap), "l"(b[j]));
                }
            }
        }
        __syncthreads();
    }

#pragma unroll
    for (int i = 0; i < 8; i++) {
        int mg = bm * BM + m0 + i;
        if (mg >= M) break;
        float bv = bias[mg];
        float lo[4], hi[4];
#pragma unroll
        for (int j = 0; j < 4; j++) {
            asm("mov.b64 {%0, %1}, %2;" : "=f"(lo[j]), "=f"(hi[j]) : "l"(acc[i * 4 + j]));
            lo[j] += bv; hi[j] += bv;
            if (doRelu) { lo[j] = fmaxf(lo[j], 0.f); hi[j] = fmaxf(hi[j], 0.f); }
        }
        float* Cp = C + (size_t)mg * NSP + bn * BN + n0;
        *(float4*)(Cp)     = make_float4(lo[0], hi[0], lo[1], hi[1]);
        *(float4*)(Cp + 4) = make_float4(lo[2], hi[2], lo[3], hi[3]);
    }
}

// ---------------------------------------------------------------------------
// Offset conv as implicit GEMM (fused im2col): d[108][p] = ow * im2col(in).
// BM=64, BN=128, BK=16, 256 threads, 4x8 per-thread tile.
// B tile element (r, p): r -> (c = r/27, k = r%27), value = in[c, p + tap_k]
// with zero padding. The 4 cols of a float4 never cross a W-row boundary.
// ---------------------------------------------------------------------------
#define OBM 64

__device__ __forceinline__ float4 im2col4(const float* __restrict__ src, int r, int p0) {
    int c  = r / 27;
    int k  = r - c * 27;
    int kd = k / 9;
    int k9 = k - kd * 9;
    int kh = k9 / 3;
    int kw = k9 - kh * 3;
    int z  = (p0 >> 10) + kd - 1;
    int y  = ((p0 >> 5) & 31) + kh - 1;
    int x0 = (p0 & 31) + kw - 1;
    float4 v = make_float4(0.f, 0.f, 0.f, 0.f);
    if ((unsigned)z < DD && (unsigned)y < HH) {
        const float* base = src + c * NSP + (z << 10) + (y << 5);
        if ((unsigned)(x0 + 0) < WW) v.x = base[x0 + 0];
        if ((unsigned)(x0 + 1) < WW) v.y = base[x0 + 1];
        if ((unsigned)(x0 + 2) < WW) v.z = base[x0 + 2];
        if ((unsigned)(x0 + 3) < WW) v.w = base[x0 + 3];
    }
    return v;
}

__global__ __launch_bounds__(256) void sgemm_off(
    const float* __restrict__ A, const float* __restrict__ X,
    const float* __restrict__ bias, float* __restrict__ C)
{
    __shared__ float As[BK][OBM];
    __shared__ float Bs[BK][BN];

    const int M = 108;
    int tid = threadIdx.x;
    int bm = blockIdx.y, bn = blockIdx.x;

    int ar = tid >> 2;               // 0..63
    int ac = (tid & 3) << 2;
    int aRow = bm * OBM + ar;
    const float* Aptr = A + (size_t)aRow * CK + ac;

    int br0 = tid >> 5;              // 0..7
    int bc0 = (tid & 31) << 2;       // 0..124
    int pg  = bn * BN + bc0;         // global col for this thread's B chunk

    int m0 = (tid >> 4) << 2;
    int c0 = (tid & 15) << 2;

    float4 aReg, bReg0, bReg1;
    aReg = (aRow < M) ? *(const float4*)Aptr : make_float4(0.f,0.f,0.f,0.f);
    bReg0 = im2col4(X, br0, pg);
    bReg1 = im2col4(X, br0 + 8, pg);

    ull acc[16];
#pragma unroll
    for (int i = 0; i < 16; i++) acc[i] = 0ull;

    const int KT = CK / BK;  // 432
    for (int kt = 0; kt < KT; kt++) {
        As[ac + 0][ar] = aReg.x; As[ac + 1][ar] = aReg.y;
        As[ac + 2][ar] = aReg.z; As[ac + 3][ar] = aReg.w;
        *(float4*)&Bs[br0][bc0]     = bReg0;
        *(float4*)&Bs[br0 + 8][bc0] = bReg1;
        __syncthreads();

        if (kt + 1 < KT) {
            aReg = (aRow < M) ? *(const float4*)(Aptr + (size_t)(kt + 1) * BK)
                              : make_float4(0.f,0.f,0.f,0.f);
            int rb = (kt + 1) * BK;
            bReg0 = im2col4(X, rb + br0, pg);
            bReg1 = im2col4(X, rb + br0 + 8, pg);
        }

#pragma unroll
        for (int kk = 0; kk < BK; kk++) {
            float4 a4 = *(const float4*)&As[kk][m0];
            const ull* b2a = (const ull*)&Bs[kk][c0];
            const ull* b2b = (const ull*)&Bs[kk][c0 + 64];
            ull bp[4] = { b2a[0], b2a[1], b2b[0], b2b[1] };
            float am[4] = { a4.x, a4.y, a4.z, a4.w };
#pragma unroll
            for (int i = 0; i < 4; i++) {
                ull ap;
                asm("mov.b64 %0, {%1, %1};" : "=l"(ap) : "f"(am[i]));
#pragma unroll
                for (int j = 0; j < 4; j++) {
                    asm("fma.rn.f32x2 %0, %1, %2, %0;"
                        : "+l"(acc[i * 4 + j]) : "l"(ap), "l"(bp[j]));
                }
            }
        }
        __syncthreads();
    }

#pragma unroll
    for (int i = 0; i < 4; i++) {
        int mg = bm * OBM + m0 + i;
        if (mg >= M) break;
        float bv = bias[mg];
        float lo[4], hi[4];
#pragma unroll
        for (int j = 0; j < 4; j++) {
            asm("mov.b64 {%0, %1}, %2;" : "=f"(lo[j]), "=f"(hi[j]) : "l"(acc[i * 4 + j]));
            lo[j] += bv; hi[j] += bv;
        }
        float* Cp = C + (size_t)mg * NSP + bn * BN;
        *(float4*)(Cp + c0)      = make_float4(lo[0], hi[0], lo[1], hi[1]);
        *(float4*)(Cp + c0 + 64) = make_float4(lo[2], hi[2], lo[3], hi[3]);
    }
}

// ---------------------------------------------------------------------------
// Driver
// ---------------------------------------------------------------------------
extern "C" void kernel_launch(void* const* d_in, const int* in_sizes, int n_in,
                              void* d_out, int out_size) {
    (void)in_sizes; (void)n_in; (void)out_size;
    const float* x = (const float*)d_in[0];
    const float* ow[4] = { (const float*)d_in[1], (const float*)d_in[5],
                           (const float*)d_in[9], (const float*)d_in[13] };
    const float* ob[4] = { (const float*)d_in[2], (const float*)d_in[6],
                           (const float*)d_in[10], (const float*)d_in[14] };
    const float* w[4]  = { (const float*)d_in[3], (const float*)d_in[7],
                           (const float*)d_in[11], (const float*)d_in[15] };
    const float* b[4]  = { (const float*)d_in[4], (const float*)d_in[8],
                           (const float*)d_in[12], (const float*)d_in[16] };
    float* out = (float*)d_out;

    float *S, *dbuf, *hbuf;
    cudaGetSymbolAddress((void**)&S,    g_S);
    cudaGetSymbolAddress((void**)&dbuf, g_d);
    cudaGetSymbolAddress((void**)&hbuf, g_h);
    float* h0 = hbuf;
    float* h1 = hbuf + (size_t)CIN * NSP;

    dim3 sampleGrid(NSP / 128, K27);
    dim3 offGrid(NSP / BN, 2);                 // 64 x 2 (rows 0-63, 64-107)
    dim3 mainGrid(NSP / BN, CIN / BM);         // 64 x 2

    const float* in = x;
    for (int L = 0; L < 3; L++) {
        sgemm_off<<<offGrid, 256>>>(ow[L], in, ob[L], dbuf);
        sample_kernel<<<sampleGrid, 128>>>(in, dbuf, S);
        float* hn = (L & 1) ? h1 : h0;
        sgemm128<<<mainGrid, 256>>>(w[L], S, b[L], hn, CIN, 1);
        in = hn;
    }
    // final: offsets from conv(h3), deformable conv applied to ORIGINAL x, no ReLU
    sgemm_off<<<offGrid, 256>>>(ow[3], in, ob[3], dbuf);
    sample_kernel<<<sampleGrid, 128>>>(x, dbuf, S);
    sgemm128<<<mainGrid, 256>>>(w[3], S, b[3], out, CIN, 0);
}

// round 6
// speedup vs baseline: 1.1925x; 1.1186x over previous
#include <cuda_runtime.h>
#include <math.h>

// Problem constants
#define NSP   8192          // D*H*W = 8*32*32
#define CIN   256
#define K27   27
#define CK    6912          // CIN * 27
#define CKH   3456          // CK / 2 (split-K half)
#define DD    8
#define HH    32
#define WW    32

typedef unsigned long long ull;

// Scratch (allocation-free rule: __device__ globals)
__device__ float g_S[CK * NSP];          // sampled matrix [c*27+k][p]  (~226.5 MB)
__device__ float g_d[108 * NSP];         // offset-conv output (108 channels)
__device__ float g_h[2][CIN * NSP];      // hidden ping-pong
__device__ float g_dp[2][108 * NSP];     // split-K partials, offset conv
__device__ float g_hp[2][CIN * NSP];     // split-K partials, main conv

// ---------------------------------------------------------------------------
// Deformable sampling: per (k,p) compute trilinear corner weights once
// (incl. validity mask and sigmoid modulation), then sweep channels.
// ---------------------------------------------------------------------------
__global__ void sample_kernel(const float* __restrict__ src,
                              const float* __restrict__ dd,
                              float* __restrict__ S) {
    int p = blockIdx.x * 128 + threadIdx.x;   // grid.x = 64
    int k = blockIdx.y;                        // 27
    int z = p >> 10, y = (p >> 5) & 31, x = p & 31;
    int kd = k / 9, kh = (k / 3) % 3, kw = k % 3;

    float cd = (float)(z + kd - 1) + dd[(k * 3 + 0) * NSP + p];
    float ch = (float)(y + kh - 1) + dd[(k * 3 + 1) * NSP + p];
    float cw = (float)(x + kw - 1) + dd[(k * 3 + 2) * NSP + p];
    float m  = 1.0f / (1.0f + expf(-dd[(81 + k) * NSP + p]));

    float d0 = floorf(cd), h0 = floorf(ch), w0 = floorf(cw);
    float fd = cd - d0, fh = ch - h0, fw = cw - w0;
    int z0 = (int)d0, y0 = (int)h0, x0 = (int)w0;

    float wt[8]; int idx[8];
#pragma unroll
    for (int j = 0; j < 8; j++) {
        int dz = (j >> 2) & 1, dy = (j >> 1) & 1, dx = j & 1;
        int zi = z0 + dz, yi = y0 + dy, xi = x0 + dx;
        float w = (dz ? fd : 1.0f - fd) * (dy ? fh : 1.0f - fh) * (dx ? fw : 1.0f - fw);
        bool valid = ((unsigned)zi < DD) && ((unsigned)yi < HH) && ((unsigned)xi < WW);
        wt[j] = valid ? (w * m) : 0.0f;
        int zc = min(max(zi, 0), DD - 1);
        int yc = min(max(yi, 0), HH - 1);
        int xc = min(max(xi, 0), WW - 1);
        idx[j] = (zc << 10) + (yc << 5) + xc;
    }

    float* out = S + (size_t)k * NSP + p;
#pragma unroll 4
    for (int c = 0; c < CIN; c++) {
        const float* b = src + c * NSP;
        float acc = wt[0] * b[idx[0]] + wt[1] * b[idx[1]]
                  + wt[2] * b[idx[2]] + wt[3] * b[idx[3]]
                  + wt[4] * b[idx[4]] + wt[5] * b[idx[5]]
                  + wt[6] * b[idx[6]] + wt[7] * b[idx[7]];
        out[(size_t)c * K27 * NSP] = acc;
    }
}

// ---------------------------------------------------------------------------
// Split-K combine: C[m][p] = (relu?) (P0[m][p] + P1[m][p] + bias[m])
// ---------------------------------------------------------------------------
__global__ __launch_bounds__(256) void combine_kernel(
    const float* __restrict__ P0, const float* __restrict__ P1,
    const float* __restrict__ bias, float* __restrict__ C,
    int total4, int doRelu)
{
    int i = blockIdx.x * 256 + threadIdx.x;
    if (i >= total4) return;
    int row = (i << 2) >> 13;           // (i*4)/NSP
    float bv = bias[row];
    float4 a = ((const float4*)P0)[i];
    float4 b = ((const float4*)P1)[i];
    float4 r;
    r.x = a.x + b.x + bv; r.y = a.y + b.y + bv;
    r.z = a.z + b.z + bv; r.w = a.w + b.w + bv;
    if (doRelu) {
        r.x = fmaxf(r.x, 0.f); r.y = fmaxf(r.y, 0.f);
        r.z = fmaxf(r.z, 0.f); r.w = fmaxf(r.w, 0.f);
    }
    ((float4*)C)[i] = r;
}

// ---------------------------------------------------------------------------
// Main SGEMM, split-K: Part[z][M][8192] = A[M][z*3456 : (z+1)*3456] * S[...].
// BM=128, BN=128, BK=16, 256 threads, 8x8 per-thread tile, f32x2 FFMA core.
// blockIdx.z = K-split. Raw partials (no bias/relu) -> combine_kernel.
// ---------------------------------------------------------------------------
#define BM 128
#define BN 128
#define BK 16

__global__ __launch_bounds__(256, 2) void sgemm128_sk(
    const float* __restrict__ A, const float* __restrict__ B,
    float* __restrict__ Part, int M)
{
    __shared__ float As[BK][BM];
    __shared__ float Bs[BK][BN];

    int tid = threadIdx.x;
    int bm = blockIdx.y, bn = blockIdx.x;
    int kOff = blockIdx.z * CKH;

    int ar0 = tid >> 2;               // 0..63
    int ac  = (tid & 3) << 2;         // 0,4,8,12
    int aRow0 = bm * BM + ar0;
    int aRow1 = aRow0 + 64;
    const float* Ap0 = A + (size_t)aRow0 * CK + kOff + ac;
    const float* Ap1 = A + (size_t)aRow1 * CK + kOff + ac;

    int br = tid >> 5;                // 0..7
    int bc = (tid & 31) << 2;         // 0..124
    const float* Bp = B + (size_t)kOff * NSP + (size_t)bn * BN;

    int m0 = (tid >> 4) << 3;
    int n0 = (tid & 15) << 3;

    float4 aR0, aR1, bR0, bR1;
    aR0 = (aRow0 < M) ? *(const float4*)Ap0 : make_float4(0.f,0.f,0.f,0.f);
    aR1 = (aRow1 < M) ? *(const float4*)Ap1 : make_float4(0.f,0.f,0.f,0.f);
    bR0 = *(const float4*)(Bp + (size_t)br * NSP + bc);
    bR1 = *(const float4*)(Bp + (size_t)(br + 8) * NSP + bc);

    ull acc[32];
#pragma unroll
    for (int i = 0; i < 32; i++) acc[i] = 0ull;

    const int KT = CKH / BK;  // 216
    for (int kt = 0; kt < KT; kt++) {
        As[ac + 0][ar0] = aR0.x; As[ac + 1][ar0] = aR0.y;
        As[ac + 2][ar0] = aR0.z; As[ac + 3][ar0] = aR0.w;
        As[ac + 0][ar0 + 64] = aR1.x; As[ac + 1][ar0 + 64] = aR1.y;
        As[ac + 2][ar0 + 64] = aR1.z; As[ac + 3][ar0 + 64] = aR1.w;
        *(float4*)&Bs[br][bc]     = bR0;
        *(float4*)&Bs[br + 8][bc] = bR1;
        __syncthreads();

        if (kt + 1 < KT) {
            size_t ka = (size_t)(kt + 1) * BK;
            aR0 = (aRow0 < M) ? *(const float4*)(Ap0 + ka) : make_float4(0.f,0.f,0.f,0.f);
            aR1 = (aRow1 < M) ? *(const float4*)(Ap1 + ka) : make_float4(0.f,0.f,0.f,0.f);
            const float* Bn = Bp + (size_t)(kt + 1) * BK * NSP;
            bR0 = *(const float4*)(Bn + (size_t)br * NSP + bc);
            bR1 = *(const float4*)(Bn + (size_t)(br + 8) * NSP + bc);
        }

#pragma unroll
        for (int kk = 0; kk < BK; kk++) {
            float4 a0 = *(const float4*)&As[kk][m0];
            float4 a1 = *(const float4*)&As[kk][m0 + 4];
            const ull* bp = (const ull*)&Bs[kk][n0];
            ull b[4] = { bp[0], bp[1], bp[2], bp[3] };
            float am[8] = { a0.x, a0.y, a0.z, a0.w, a1.x, a1.y, a1.z, a1.w };
#pragma unroll
            for (int i = 0; i < 8; i++) {
                ull ap;
                asm("mov.b64 %0, {%1, %1};" : "=l"(ap) : "f"(am[i]));
#pragma unroll
                for (int j = 0; j < 4; j++) {
                    asm("fma.rn.f32x2 %0, %1, %2, %0;"
                        : "+l"(acc[i * 4 + j]) : "l"(ap), "l"(b[j]));
                }
            }
        }
        __syncthreads();
    }

    float* Pz = Part + (size_t)blockIdx.z * M * NSP;
#pragma unroll
    for (int i = 0; i < 8; i++) {
        int mg = bm * BM + m0 + i;
        if (mg >= M) break;
        float lo[4], hi[4];
#pragma unroll
        for (int j = 0; j < 4; j++) {
            asm("mov.b64 {%0, %1}, %2;" : "=f"(lo[j]), "=f"(hi[j]) : "l"(acc[i * 4 + j]));
        }
        float* Cp = Pz + (size_t)mg * NSP + bn * BN + n0;
        *(float4*)(Cp)     = make_float4(lo[0], hi[0], lo[1], hi[1]);
        *(float4*)(Cp + 4) = make_float4(lo[2], hi[2], lo[3], hi[3]);
    }
}

// ---------------------------------------------------------------------------
// Offset conv as implicit GEMM (fused im2col), split-K.
// BM=64, BN=128, BK=16, 256 threads, 4x8 per-thread tile.
// ---------------------------------------------------------------------------
#define OBM 64

__device__ __forceinline__ float4 im2col4(const float* __restrict__ src, int r, int p0) {
    int c  = r / 27;
    int k  = r - c * 27;
    int kd = k / 9;
    int k9 = k - kd * 9;
    int kh = k9 / 3;
    int kw = k9 - kh * 3;
    int z  = (p0 >> 10) + kd - 1;
    int y  = ((p0 >> 5) & 31) + kh - 1;
    int x0 = (p0 & 31) + kw - 1;
    float4 v = make_float4(0.f, 0.f, 0.f, 0.f);
    if ((unsigned)z < DD && (unsigned)y < HH) {
        const float* base = src + c * NSP + (z << 10) + (y << 5);
        if ((unsigned)(x0 + 0) < WW) v.x = base[x0 + 0];
        if ((unsigned)(x0 + 1) < WW) v.y = base[x0 + 1];
        if ((unsigned)(x0 + 2) < WW) v.z = base[x0 + 2];
        if ((unsigned)(x0 + 3) < WW) v.w = base[x0 + 3];
    }
    return v;
}

__global__ __launch_bounds__(256, 2) void sgemm_off_sk(
    const float* __restrict__ A, const float* __restrict__ X,
    float* __restrict__ Part)
{
    __shared__ float As[BK][OBM];
    __shared__ float Bs[BK][BN];

    const int M = 108;
    int tid = threadIdx.x;
    int bm = blockIdx.y, bn = blockIdx.x;
    int kOff = blockIdx.z * CKH;

    int ar = tid >> 2;               // 0..63
    int ac = (tid & 3) << 2;
    int aRow = bm * OBM + ar;
    const float* Aptr = A + (size_t)aRow * CK + kOff + ac;

    int br0 = tid >> 5;              // 0..7
    int bc0 = (tid & 31) << 2;       // 0..124
    int pg  = bn * BN + bc0;

    int m0 = (tid >> 4) << 2;
    int c0 = (tid & 15) << 2;

    float4 aReg, bReg0, bReg1;
    aReg = (aRow < M) ? *(const float4*)Aptr : make_float4(0.f,0.f,0.f,0.f);
    bReg0 = im2col4(X, kOff + br0, pg);
    bReg1 = im2col4(X, kOff + br0 + 8, pg);

    ull acc[16];
#pragma unroll
    for (int i = 0; i < 16; i++) acc[i] = 0ull;

    const int KT = CKH / BK;  // 216
    for (int kt = 0; kt < KT; kt++) {
        As[ac + 0][ar] = aReg.x; As[ac + 1][ar] = aReg.y;
        As[ac + 2][ar] = aReg.z; As[ac + 3][ar] = aReg.w;
        *(float4*)&Bs[br0][bc0]     = bReg0;
        *(float4*)&Bs[br0 + 8][bc0] = bReg1;
        __syncthreads();

        if (kt + 1 < KT) {
            aReg = (aRow < M) ? *(const float4*)(Aptr + (size_t)(kt + 1) * BK)
                              : make_float4(0.f,0.f,0.f,0.f);
            int rb = kOff + (kt + 1) * BK;
            bReg0 = im2col4(X, rb + br0, pg);
            bReg1 = im2col4(X, rb + br0 + 8, pg);
        }

#pragma unroll
        for (int kk = 0; kk < BK; kk++) {
            float4 a4 = *(const float4*)&As[kk][m0];
            const ull* b2a = (const ull*)&Bs[kk][c0];
            const ull* b2b = (const ull*)&Bs[kk][c0 + 64];
            ull bp[4] = { b2a[0], b2a[1], b2b[0], b2b[1] };
            float am[4] = { a4.x, a4.y, a4.z, a4.w };
#pragma unroll
            for (int i = 0; i < 4; i++) {
                ull ap;
                asm("mov.b64 %0, {%1, %1};" : "=l"(ap) : "f"(am[i]));
#pragma unroll
                for (int j = 0; j < 4; j++) {
                    asm("fma.rn.f32x2 %0, %1, %2, %0;"
                        : "+l"(acc[i * 4 + j]) : "l"(ap), "l"(bp[j]));
                }
            }
        }
        __syncthreads();
    }

    float* Pz = Part + (size_t)blockIdx.z * M * NSP;
#pragma unroll
    for (int i = 0; i < 4; i++) {
        int mg = bm * OBM + m0 + i;
        if (mg >= M) break;
        float lo[4], hi[4];
#pragma unroll
        for (int j = 0; j < 4; j++) {
            asm("mov.b64 {%0, %1}, %2;" : "=f"(lo[j]), "=f"(hi[j]) : "l"(acc[i * 4 + j]));
        }
        float* Cp = Pz + (size_t)mg * NSP + bn * BN;
        *(float4*)(Cp + c0)      = make_float4(lo[0], hi[0], lo[1], hi[1]);
        *(float4*)(Cp + c0 + 64) = make_float4(lo[2], hi[2], lo[3], hi[3]);
    }
}

// ---------------------------------------------------------------------------
// Driver
// ---------------------------------------------------------------------------
extern "C" void kernel_launch(void* const* d_in, const int* in_sizes, int n_in,
                              void* d_out, int out_size) {
    (void)in_sizes; (void)n_in; (void)out_size;
    const float* x = (const float*)d_in[0];
    const float* ow[4] = { (const float*)d_in[1], (const float*)d_in[5],
                           (const float*)d_in[9], (const float*)d_in[13] };
    const float* ob[4] = { (const float*)d_in[2], (const float*)d_in[6],
                           (const float*)d_in[10], (const float*)d_in[14] };
    const float* w[4]  = { (const float*)d_in[3], (const float*)d_in[7],
                           (const float*)d_in[11], (const float*)d_in[15] };
    const float* b[4]  = { (const float*)d_in[4], (const float*)d_in[8],
                           (const float*)d_in[12], (const float*)d_in[16] };
    float* out = (float*)d_out;

    float *S, *dbuf, *hbuf, *dp, *hp;
    cudaGetSymbolAddress((void**)&S,    g_S);
    cudaGetSymbolAddress((void**)&dbuf, g_d);
    cudaGetSymbolAddress((void**)&hbuf, g_h);
    cudaGetSymbolAddress((void**)&dp,   g_dp);
    cudaGetSymbolAddress((void**)&hp,   g_hp);
    float* h0 = hbuf;
    float* h1 = hbuf + (size_t)CIN * NSP;

    dim3 sampleGrid(NSP / 128, K27);
    dim3 offGrid(NSP / BN, 2, 2);               // 64 x 2 x splitK2 = 256 CTAs
    dim3 mainGrid(NSP / BN, CIN / BM, 2);       // 64 x 2 x splitK2 = 256 CTAs
    int offTot4  = 108 * NSP / 4;
    int mainTot4 = CIN * NSP / 4;
    int offCombBlocks  = (offTot4 + 255) / 256;
    int mainCombBlocks = (mainTot4 + 255) / 256;

    const float* in = x;
    for (int L = 0; L < 3; L++) {
        sgemm_off_sk<<<offGrid, 256>>>(ow[L], in, dp);
        combine_kernel<<<offCombBlocks, 256>>>(dp, dp + (size_t)108 * NSP,
                                               ob[L], dbuf, offTot4, 0);
        sample_kernel<<<sampleGrid, 128>>>(in, dbuf, S);
        float* hn = (L & 1) ? h1 : h0;
        sgemm128_sk<<<mainGrid, 256>>>(w[L], S, hp, CIN);
        combine_kernel<<<mainCombBlocks, 256>>>(hp, hp + (size_t)CIN * NSP,
                                                b[L], hn, mainTot4, 1);
        in = hn;
    }
    // final: offsets from conv(h3), deformable conv applied to ORIGINAL x, no ReLU
    sgemm_off_sk<<<offGrid, 256>>>(ow[3], in, dp);
    combine_kernel<<<offCombBlocks, 256>>>(dp, dp + (size_t)108 * NSP,
                                           ob[3], dbuf, offTot4, 0);
    sample_kernel<<<sampleGrid, 128>>>(x, dbuf, S);
    sgemm128_sk<<<mainGrid, 256>>>(w[3], S, hp, CIN);
    combine_kernel<<<mainCombBlocks, 256>>>(hp, hp + (size_t)CIN * NSP,
                                            b[3], out, mainTot4, 0);
}

// round 9
// speedup vs baseline: 1.7261x; 1.4475x over previous
#include <cuda_runtime.h>
#include <cuda_bf16.h>
#include <math.h>
#include <stdint.h>

// Problem constants
#define NSP   8192          // D*H*W = 8*32*32
#define CIN   256
#define K27   27
#define CK    6912          // CIN * 27
#define CKH   3456          // CK / 2 (split-K half, offset path)
#define DD    8
#define HH    32
#define WW    32

typedef unsigned long long ull;

// Scratch (allocation-free rule: __device__ globals)
__device__ __nv_bfloat16 g_Shi[(size_t)CK * NSP];   // sampled matrix hi limb
__device__ __nv_bfloat16 g_Slo[(size_t)CK * NSP];   // sampled matrix lo limb
__device__ __nv_bfloat16 g_Whi[(size_t)CIN * CK];   // main weights hi limb
__device__ __nv_bfloat16 g_Wlo[(size_t)CIN * CK];   // main weights lo limb
__device__ float g_d[108 * NSP];                    // offset-conv output
__device__ float g_h[2][CIN * NSP];                 // hidden ping-pong
__device__ float g_dp[2][108 * NSP];                // split-K partials, offset conv

// ===========================================================================
// PTX helpers
// ===========================================================================
__device__ __forceinline__ uint32_t smem_u32(const void* p) {
    uint32_t a;
    asm("{ .reg .u64 t; cvta.to.shared.u64 t, %1; cvt.u32.u64 %0, t; }" : "=r"(a) : "l"(p));
    return a;
}
__device__ __forceinline__ void cp16(uint32_t dst, const void* src) {
    asm volatile("cp.async.cg.shared.global [%0], [%1], 16;" :: "r"(dst), "l"(src));
}
__device__ __forceinline__ void cp_commit() {
    asm volatile("cp.async.commit_group;" ::: "memory");
}
template <int N>
__device__ __forceinline__ void cp_wait() {
    asm volatile("cp.async.wait_group %0;" :: "n"(N) : "memory");
}
__device__ __forceinline__ void ldsm4(uint32_t* r, uint32_t addr) {
    asm volatile("ldmatrix.sync.aligned.m8n8.x4.shared.b16 {%0,%1,%2,%3}, [%4];"
                 : "=r"(r[0]), "=r"(r[1]), "=r"(r[2]), "=r"(r[3]) : "r"(addr));
}
__device__ __forceinline__ void ldsm4t(uint32_t* r, uint32_t addr) {
    asm volatile("ldmatrix.sync.aligned.m8n8.x4.trans.shared.b16 {%0,%1,%2,%3}, [%4];"
                 : "=r"(r[0]), "=r"(r[1]), "=r"(r[2]), "=r"(r[3]) : "r"(addr));
}
__device__ __forceinline__ void mma_bf16(float* d, const uint32_t* a, uint32_t b0, uint32_t b1) {
    asm volatile("mma.sync.aligned.m16n8k16.row.col.f32.bf16.bf16.f32 "
                 "{%0,%1,%2,%3}, {%4,%5,%6,%7}, {%8,%9}, {%0,%1,%2,%3};"
                 : "+f"(d[0]), "+f"(d[1]), "+f"(d[2]), "+f"(d[3])
                 : "r"(a[0]), "r"(a[1]), "r"(a[2]), "r"(a[3]), "r"(b0), "r"(b1));
}

// ===========================================================================
// Weight limb-split prep: fp32 -> (hi, lo) bf16
// ===========================================================================
__global__ __launch_bounds__(256) void split_kernel(
    const float* __restrict__ src, __nv_bfloat16* __restrict__ hi,
    __nv_bfloat16* __restrict__ lo, int n)
{
    int i = blockIdx.x * 256 + threadIdx.x;
    if (i >= n) return;
    float a = src[i];
    __nv_bfloat16 h = __float2bfloat16(a);
    hi[i] = h;
    lo[i] = __float2bfloat16(a - __bfloat162float(h));
}

// ===========================================================================
// Deformable sampling -> bf16 limb-split S  (S[(c*27+k)][p])
// ===========================================================================
__global__ void sample_kernel(const float* __restrict__ src,
                              const float* __restrict__ dd,
                              __nv_bfloat16* __restrict__ Shi,
                              __nv_bfloat16* __restrict__ Slo) {
    int p = blockIdx.x * 128 + threadIdx.x;   // grid.x = 64
    int k = blockIdx.y;                        // 27
    int z = p >> 10, y = (p >> 5) & 31, x = p & 31;
    int kd = k / 9, kh = (k / 3) % 3, kw = k % 3;

    float cd = (float)(z + kd - 1) + dd[(k * 3 + 0) * NSP + p];
    float ch = (float)(y + kh - 1) + dd[(k * 3 + 1) * NSP + p];
    float cw = (float)(x + kw - 1) + dd[(k * 3 + 2) * NSP + p];
    float m  = 1.0f / (1.0f + expf(-dd[(81 + k) * NSP + p]));

    float d0 = floorf(cd), h0 = floorf(ch), w0 = floorf(cw);
    float fd = cd - d0, fh = ch - h0, fw = cw - w0;
    int z0 = (int)d0, y0 = (int)h0, x0 = (int)w0;

    float wt[8]; int idx[8];
#pragma unroll
    for (int j = 0; j < 8; j++) {
        int dz = (j >> 2) & 1, dy = (j >> 1) & 1, dx = j & 1;
        int zi = z0 + dz, yi = y0 + dy, xi = x0 + dx;
        float w = (dz ? fd : 1.0f - fd) * (dy ? fh : 1.0f - fh) * (dx ? fw : 1.0f - fw);
        bool valid = ((unsigned)zi < DD) && ((unsigned)yi < HH) && ((unsigned)xi < WW);
        wt[j] = valid ? (w * m) : 0.0f;
        int zc = min(max(zi, 0), DD - 1);
        int yc = min(max(yi, 0), HH - 1);
        int xc = min(max(xi, 0), WW - 1);
        idx[j] = (zc << 10) + (yc << 5) + xc;
    }

    size_t base = (size_t)k * NSP + p;
#pragma unroll 4
    for (int c = 0; c < CIN; c++) {
        const float* b = src + c * NSP;
        float acc = wt[0] * b[idx[0]] + wt[1] * b[idx[1]]
                  + wt[2] * b[idx[2]] + wt[3] * b[idx[3]]
                  + wt[4] * b[idx[4]] + wt[5] * b[idx[5]]
                  + wt[6] * b[idx[6]] + wt[7] * b[idx[7]];
        __nv_bfloat16 hv = __float2bfloat16(acc);
        size_t o = base + (size_t)c * K27 * NSP;
        Shi[o] = hv;
        Slo[o] = __float2bfloat16(acc - __bfloat162float(hv));
    }
}

// ===========================================================================
// Main GEMM on tensor cores (mma.sync bf16, 2-limb split):
// C[256][8192] = W[256][6912] * S[6912][8192] + bias (+ReLU)
// CTA: 128(M) x 64(N), BK=32. 8 warps: wm = wid&3 (32 rows), wn = wid>>2 (32 cols).
// A smem rows padded to 40 bf16 (80B), B rows to 72 bf16 (144B): ldmatrix
// conflict-free. cp.async double-buffered.
// ===========================================================================
#define ASZ   (128 * 40 * 2)      // 10240 B per A limb tile
#define BSZ   (32 * 72 * 2)       // 4608 B per B limb tile
#define STAGE (2 * ASZ + 2 * BSZ) // 29696 B
#define SMTOT (2 * STAGE)         // 59392 B
#define KTILES (CK / 32)          // 216

__global__ __launch_bounds__(256) void mma_gemm(
    const __nv_bfloat16* __restrict__ Ahi, const __nv_bfloat16* __restrict__ Alo,
    const __nv_bfloat16* __restrict__ Bhi, const __nv_bfloat16* __restrict__ Blo,
    const float* __restrict__ bias, float* __restrict__ C, int doRelu)
{
    extern __shared__ char smem[];
    uint32_t sb = smem_u32(smem);
    int tid = threadIdx.x;
    int wid = tid >> 5, lid = tid & 31;
    int p0 = blockIdx.x * 64;          // N tile base
    int mBase = blockIdx.y * 128;      // M tile base

    int wm = wid & 3;                  // 0..3 -> 32 rows each
    int wn = wid >> 2;                 // 0..1 -> 32 cols each
    int quad = lid >> 3, rr = lid & 7;

    // loader indices
    int aRow = tid >> 2;               // 0..63 (x2 with +64)
    int aU   = tid & 3;                // 16B unit in 64B row
    int bRow = tid >> 3;               // 0..31
    int bU   = tid & 7;                // 16B unit in 128B row

    float acc[2][4][4];
#pragma unroll
    for (int i = 0; i < 2; i++)
#pragma unroll
        for (int j = 0; j < 4; j++)
#pragma unroll
            for (int q = 0; q < 4; q++) acc[i][j][q] = 0.f;

    // ---- stage issue ----
    auto issue = [&](int buf, int kt) {
        uint32_t s = sb + buf * STAGE;
        int kOff = kt * 32;
        // A hi/lo: 128 rows x 64B, 2 rows-per-thread (aRow, aRow+64)
#pragma unroll
        for (int t = 0; t < 2; t++) {
            int row = aRow + t * 64;
            uint32_t d = s + row * 80 + aU * 16;
            const __nv_bfloat16* sh = Ahi + (size_t)(mBase + row) * CK + kOff + aU * 8;
            const __nv_bfloat16* sl = Alo + (size_t)(mBase + row) * CK + kOff + aU * 8;
            cp16(d, sh);
            cp16(d + ASZ, sl);
        }
        // B hi/lo: 32 rows x 128B, 1 chunk per thread
        {
            uint32_t d = s + 2 * ASZ + bRow * 144 + bU * 16;
            const __nv_bfloat16* sh = Bhi + (size_t)(kOff + bRow) * NSP + p0 + bU * 8;
            const __nv_bfloat16* sl = Blo + (size_t)(kOff + bRow) * NSP + p0 + bU * 8;
            cp16(d, sh);
            cp16(d + BSZ, sl);
        }
        cp_commit();
    };

    issue(0, 0);

    for (int kt = 0; kt < KTILES; kt++) {
        int buf = kt & 1;
        if (kt + 1 < KTILES) {
            issue(buf ^ 1, kt + 1);
            cp_wait<1>();
        } else {
            cp_wait<0>();
        }
        __syncthreads();

        uint32_t s = sb + buf * STAGE;
#pragma unroll
        for (int ks = 0; ks < 2; ks++) {
            int k0 = ks * 16;
            // A fragments (2 m-frags x 4 regs), hi + lo
            uint32_t ah[2][4], al[2][4];
#pragma unroll
            for (int mf = 0; mf < 2; mf++) {
                int row = wm * 32 + mf * 16 + ((quad & 1) ? 8 : 0) + rr;
                int col = k0 + ((quad >> 1) ? 8 : 0);
                uint32_t ad = s + (uint32_t)(row * 40 + col) * 2;
                ldsm4(ah[mf], ad);
                ldsm4(al[mf], ad + ASZ);
            }
            // B fragments: 2 ldmatrix.x4.trans -> 4 n-frags of (b0,b1), hi + lo
            uint32_t bh[8], bl[8];   // [nf*2 + reg]
#pragma unroll
            for (int nb = 0; nb < 2; nb++) {
                int row = k0 + ((quad & 1) ? 8 : 0) + rr;
                int col = wn * 32 + nb * 16 + ((quad >> 1) ? 8 : 0);
                uint32_t bd = s + 2 * ASZ + (uint32_t)(row * 72 + col) * 2;
                uint32_t t[4];
                ldsm4t(t, bd);
                bh[nb * 4 + 0] = t[0]; bh[nb * 4 + 1] = t[1];
                bh[nb * 4 + 2] = t[2]; bh[nb * 4 + 3] = t[3];
                ldsm4t(t, bd + BSZ);
                bl[nb * 4 + 0] = t[0]; bl[nb * 4 + 1] = t[1];
                bl[nb * 4 + 2] = t[2]; bl[nb * 4 + 3] = t[3];
            }
#pragma unroll
            for (int mf = 0; mf < 2; mf++) {
#pragma unroll
                for (int nf = 0; nf < 4; nf++) {
                    uint32_t b0h = bh[nf * 2], b1h = bh[nf * 2 + 1];
                    uint32_t b0l = bl[nf * 2], b1l = bl[nf * 2 + 1];
                    mma_bf16(acc[mf][nf], ah[mf], b0h, b1h);
                    mma_bf16(acc[mf][nf], al[mf], b0h, b1h);
                    mma_bf16(acc[mf][nf], ah[mf], b0l, b1l);
                }
            }
        }
        __syncthreads();
    }

    // epilogue: bias (+ReLU), direct fp32 stores
    int g = lid >> 2, t4 = lid & 3;
#pragma unroll
    for (int mf = 0; mf < 2; mf++) {
        int row0 = mBase + wm * 32 + mf * 16 + g;
        int row1 = row0 + 8;
        float bv0 = bias[row0], bv1 = bias[row1];
#pragma unroll
        for (int nf = 0; nf < 4; nf++) {
            int col = p0 + wn * 32 + nf * 8 + 2 * t4;
            float v0 = acc[mf][nf][0] + bv0;
            float v1 = acc[mf][nf][1] + bv0;
            float v2 = acc[mf][nf][2] + bv1;
            float v3 = acc[mf][nf][3] + bv1;
            if (doRelu) {
                v0 = fmaxf(v0, 0.f); v1 = fmaxf(v1, 0.f);
                v2 = fmaxf(v2, 0.f); v3 = fmaxf(v3, 0.f);
            }
            *(float2*)(C + (size_t)row0 * NSP + col) = make_float2(v0, v1);
            *(float2*)(C + (size_t)row1 * NSP + col) = make_float2(v2, v3);
        }
    }
}

// ===========================================================================
// Split-K combine (offset path only)
// ===========================================================================
__global__ __launch_bounds__(256) void combine_kernel(
    const float* __restrict__ P0, const float* __restrict__ P1,
    const float* __restrict__ bias, float* __restrict__ C, int total4)
{
    int i = blockIdx.x * 256 + threadIdx.x;
    if (i >= total4) return;
    int row = i / (NSP / 4);
    float bv = bias[row];
    float4 a = ((const float4*)P0)[i];
    float4 b = ((const float4*)P1)[i];
    float4 r;
    r.x = a.x + b.x + bv; r.y = a.y + b.y + bv;
    r.z = a.z + b.z + bv; r.w = a.w + b.w + bv;
    ((float4*)C)[i] = r;
}

// ===========================================================================
// Offset conv: implicit-im2col SGEMM, split-K (fp32 SIMT path, unchanged)
// ===========================================================================
#define BK 16
#define BN 128
#define OBM 64

__device__ __forceinline__ float4 im2col4(const float* __restrict__ src, int r, int p0) {
    int c  = r / 27;
    int k  = r - c * 27;
    int kd = k / 9;
    int k9 = k - kd * 9;
    int kh = k9 / 3;
    int kw = k9 - kh * 3;
    int z  = (p0 >> 10) + kd - 1;
    int y  = ((p0 >> 5) & 31) + kh - 1;
    int x0 = (p0 & 31) + kw - 1;
    float4 v = make_float4(0.f, 0.f, 0.f, 0.f);
    if ((unsigned)z < DD && (unsigned)y < HH) {
        const float* base = src + c * NSP + (z << 10) + (y << 5);
        if ((unsigned)(x0 + 0) < WW) v.x = base[x0 + 0];
        if ((unsigned)(x0 + 1) < WW) v.y = base[x0 + 1];
        if ((unsigned)(x0 + 2) < WW) v.z = base[x0 + 2];
        if ((unsigned)(x0 + 3) < WW) v.w = base[x0 + 3];
    }
    return v;
}

__global__ __launch_bounds__(256, 2) void sgemm_off_sk(
    const float* __restrict__ A, const float* __restrict__ X,
    float* __restrict__ Part)
{
    __shared__ float As[BK][OBM];
    __shared__ float Bs[BK][BN];

    const int M = 108;
    int tid = threadIdx.x;
    int bm = blockIdx.y, bn = blockIdx.x;
    int kOff = blockIdx.z * CKH;

    int ar = tid >> 2;
    int ac = (tid & 3) << 2;
    int aRow = bm * OBM + ar;
    const float* Aptr = A + (size_t)aRow * CK + kOff + ac;

    int br0 = tid >> 5;
    int bc0 = (tid & 31) << 2;
    int pg  = bn * BN + bc0;

    int m0 = (tid >> 4) << 2;
    int c0 = (tid & 15) << 2;

    float4 aReg, bReg0, bReg1;
    aReg = (aRow < M) ? *(const float4*)Aptr : make_float4(0.f,0.f,0.f,0.f);
    bReg0 = im2col4(X, kOff + br0, pg);
    bReg1 = im2col4(X, kOff + br0 + 8, pg);

    ull acc[16];
#pragma unroll
    for (int i = 0; i < 16; i++) acc[i] = 0ull;

    const int KT = CKH / BK;  // 216
    for (int kt = 0; kt < KT; kt++) {
        As[ac + 0][ar] = aReg.x; As[ac + 1][ar] = aReg.y;
        As[ac + 2][ar] = aReg.z; As[ac + 3][ar] = aReg.w;
        *(float4*)&Bs[br0][bc0]     = bReg0;
        *(float4*)&Bs[br0 + 8][bc0] = bReg1;
        __syncthreads();

        if (kt + 1 < KT) {
            aReg = (aRow < M) ? *(const float4*)(Aptr + (size_t)(kt + 1) * BK)
                              : make_float4(0.f,0.f,0.f,0.f);
            int rb = kOff + (kt + 1) * BK;
            bReg0 = im2col4(X, rb + br0, pg);
            bReg1 = im2col4(X, rb + br0 + 8, pg);
        }

#pragma unroll
        for (int kk = 0; kk < BK; kk++) {
            float4 a4 = *(const float4*)&As[kk][m0];
            const ull* b2a = (const ull*)&Bs[kk][c0];
            const ull* b2b = (const ull*)&Bs[kk][c0 + 64];
            ull bp[4] = { b2a[0], b2a[1], b2b[0], b2b[1] };
            float am[4] = { a4.x, a4.y, a4.z, a4.w };
#pragma unroll
            for (int i = 0; i < 4; i++) {
                ull ap;
                asm("mov.b64 %0, {%1, %1};" : "=l"(ap) : "f"(am[i]));
#pragma unroll
                for (int j = 0; j < 4; j++) {
                    asm("fma.rn.f32x2 %0, %1, %2, %0;"
                        : "+l"(acc[i * 4 + j]) : "l"(ap), "l"(bp[j]));
                }
            }
        }
        __syncthreads();
    }

    float* Pz = Part + (size_t)blockIdx.z * M * NSP;
#pragma unroll
    for (int i = 0; i < 4; i++) {
        int mg = bm * OBM + m0 + i;
        if (mg >= M) break;
        float lo[4], hi[4];
#pragma unroll
        for (int j = 0; j < 4; j++) {
            asm("mov.b64 {%0, %1}, %2;" : "=f"(lo[j]), "=f"(hi[j]) : "l"(acc[i * 4 + j]));
        }
        float* Cp = Pz + (size_t)mg * NSP + bn * BN;
        *(float4*)(Cp + c0)      = make_float4(lo[0], hi[0], lo[1], hi[1]);
        *(float4*)(Cp + c0 + 64) = make_float4(lo[2], hi[2], lo[3], hi[3]);
    }
}

// ===========================================================================
// Driver
// ===========================================================================
extern "C" void kernel_launch(void* const* d_in, const int* in_sizes, int n_in,
                              void* d_out, int out_size) {
    (void)in_sizes; (void)n_in; (void)out_size;
    const float* x = (const float*)d_in[0];
    const float* ow[4] = { (const float*)d_in[1], (const float*)d_in[5],
                           (const float*)d_in[9], (const float*)d_in[13] };
    const float* ob[4] = { (const float*)d_in[2], (const float*)d_in[6],
                           (const float*)d_in[10], (const float*)d_in[14] };
    const float* w[4]  = { (const float*)d_in[3], (const float*)d_in[7],
                           (const float*)d_in[11], (const float*)d_in[15] };
    const float* b[4]  = { (const float*)d_in[4], (const float*)d_in[8],
                           (const float*)d_in[12], (const float*)d_in[16] };
    float* out = (float*)d_out;

    __nv_bfloat16 *Shi, *Slo, *Whi, *Wlo;
    float *dbuf, *hbuf, *dp;
    cudaGetSymbolAddress((void**)&Shi,  g_Shi);
    cudaGetSymbolAddress((void**)&Slo,  g_Slo);
    cudaGetSymbolAddress((void**)&Whi,  g_Whi);
    cudaGetSymbolAddress((void**)&Wlo,  g_Wlo);
    cudaGetSymbolAddress((void**)&dbuf, g_d);
    cudaGetSymbolAddress((void**)&hbuf, g_h);
    cudaGetSymbolAddress((void**)&dp,   g_dp);
    float* h0 = hbuf;
    float* h1 = hbuf + (size_t)CIN * NSP;

    static int smemSet = 0;
    if (!smemSet) {
        cudaFuncSetAttribute(mma_gemm, cudaFuncAttributeMaxDynamicSharedMemorySize, SMTOT);
        smemSet = 1;
    }

    dim3 sampleGrid(NSP / 128, K27);
    dim3 offGrid(NSP / BN, 2, 2);            // 64 x 2 x 2 = 256 CTAs
    dim3 tcGrid(NSP / 64, 2);                // 128 x 2 = 256 CTAs
    int offTot4 = 108 * NSP / 4;
    int offCombBlocks = (offTot4 + 255) / 256;
    int wN = CIN * CK;
    int wBlocks = (wN + 255) / 256;

    const float* in = x;
    for (int L = 0; L < 3; L++) {
        sgemm_off_sk<<<offGrid, 256>>>(ow[L], in, dp);
        combine_kernel<<<offCombBlocks, 256>>>(dp, dp + (size_t)108 * NSP,
                                               ob[L], dbuf, offTot4);
        sample_kernel<<<sampleGrid, 128>>>(in, dbuf, Shi, Slo);
        split_kernel<<<wBlocks, 256>>>(w[L], Whi, Wlo, wN);
        float* hn = (L & 1) ? h1 : h0;
        mma_gemm<<<tcGrid, 256, SMTOT>>>(Whi, Wlo, Shi, Slo, b[L], hn, 1);
        in = hn;
    }
    // final: offsets from conv(h3), deformable conv applied to ORIGINAL x, no ReLU
    sgemm_off_sk<<<offGrid, 256>>>(ow[3], in, dp);
    combine_kernel<<<offCombBlocks, 256>>>(dp, dp + (size_t)108 * NSP,
                                           ob[3], dbuf, offTot4);
    sample_kernel<<<sampleGrid, 128>>>(x, dbuf, Shi, Slo);
    split_kernel<<<wBlocks, 256>>>(w[3], Whi, Wlo, wN);
    mma_gemm<<<tcGrid, 256, SMTOT>>>(Whi, Wlo, Shi, Slo, b[3], out, 0);
}

// round 12
// speedup vs baseline: 1.9274x; 1.1166x over previous
#include <cuda_runtime.h>
#include <cuda_bf16.h>
#include <math.h>
#include <stdint.h>

// Problem constants
#define NSP   8192          // D*H*W = 8*32*32
#define CIN   256
#define K27   27
#define CK    6912          // CIN * 27
#define DD    8
#define HH    32
#define WW    32

typedef unsigned long long ull;

// Scratch (allocation-free rule: __device__ globals)
__device__ float g_d[108 * NSP];                    // offset-conv output
__device__ float g_h[2][CIN * NSP];                 // hidden ping-pong
__device__ float g_dp[2][108 * NSP];                // split-K partials (offset conv)
__device__ float g_zerobias[256];                   // zero bias for partial passes
__device__ __nv_bfloat16 g_Shi[(size_t)CK * NSP];   // im2col/sampled matrix hi limb
__device__ __nv_bfloat16 g_Slo[(size_t)CK * NSP];   // im2col/sampled matrix lo limb
__device__ __nv_bfloat16 g_Whi[(size_t)CIN * CK];   // main weights hi limb
__device__ __nv_bfloat16 g_Wlo[(size_t)CIN * CK];   // main weights lo limb
__device__ __nv_bfloat16 g_OWhi[(size_t)128 * CK];  // offset weights hi (padded to 128 rows)
__device__ __nv_bfloat16 g_OWlo[(size_t)128 * CK];  // offset weights lo

// ===========================================================================
// PTX helpers
// ===========================================================================
__device__ __forceinline__ uint32_t smem_u32(const void* p) {
    uint32_t a;
    asm("{ .reg .u64 t; cvta.to.shared.u64 t, %1; cvt.u32.u64 %0, t; }" : "=r"(a) : "l"(p));
    return a;
}
__device__ __forceinline__ void cp16(uint32_t dst, const void* src) {
    asm volatile("cp.async.cg.shared.global [%0], [%1], 16;" :: "r"(dst), "l"(src));
}
__device__ __forceinline__ void cp_commit() {
    asm volatile("cp.async.commit_group;" ::: "memory");
}
template <int N>
__device__ __forceinline__ void cp_wait() {
    asm volatile("cp.async.wait_group %0;" :: "n"(N) : "memory");
}
__device__ __forceinline__ void ldsm4(uint32_t* r, uint32_t addr) {
    asm volatile("ldmatrix.sync.aligned.m8n8.x4.shared.b16 {%0,%1,%2,%3}, [%4];"
                 : "=r"(r[0]), "=r"(r[1]), "=r"(r[2]), "=r"(r[3]) : "r"(addr));
}
__device__ __forceinline__ void ldsm4t(uint32_t* r, uint32_t addr) {
    asm volatile("ldmatrix.sync.aligned.m8n8.x4.trans.shared.b16 {%0,%1,%2,%3}, [%4];"
                 : "=r"(r[0]), "=r"(r[1]), "=r"(r[2]), "=r"(r[3]) : "r"(addr));
}
__device__ __forceinline__ void mma_bf16(float* d, const uint32_t* a, uint32_t b0, uint32_t b1) {
    asm volatile("mma.sync.aligned.m16n8k16.row.col.f32.bf16.bf16.f32 "
                 "{%0,%1,%2,%3}, {%4,%5,%6,%7}, {%8,%9}, {%0,%1,%2,%3};"
                 : "+f"(d[0]), "+f"(d[1]), "+f"(d[2]), "+f"(d[3])
                 : "r"(a[0]), "r"(a[1]), "r"(a[2]), "r"(a[3]), "r"(b0), "r"(b1));
}

// ===========================================================================
// Weight limb-split: fp32 -> (hi, lo) bf16
// ===========================================================================
__global__ __launch_bounds__(256) void split_kernel(
    const float* __restrict__ src, __nv_bfloat16* __restrict__ hi,
    __nv_bfloat16* __restrict__ lo, int n)
{
    int i = blockIdx.x * 256 + threadIdx.x;
    if (i >= n) return;
    float a = src[i];
    __nv_bfloat16 h = __float2bfloat16(a);
    hi[i] = h;
    lo[i] = __float2bfloat16(a - __bfloat162float(h));
}

// Padded variant: 128 rows, rows >= 108 are zero.
__global__ __launch_bounds__(256) void owsplit_kernel(
    const float* __restrict__ src, __nv_bfloat16* __restrict__ hi,
    __nv_bfloat16* __restrict__ lo)
{
    int i = blockIdx.x * 256 + threadIdx.x;
    if (i >= 128 * CK) return;
    int row = i / CK;
    float a = (row < 108) ? src[i] : 0.0f;
    __nv_bfloat16 h = __float2bfloat16(a);
    hi[i] = h;
    lo[i] = __float2bfloat16(a - __bfloat162float(h));
}

// ===========================================================================
// Fused im2col + limb split for the plain 3x3x3 pad-1 conv:
// S[(c*27+k)][p] = in[c, p + tap_k] (zero pad), as bf16 (hi, lo)
// ===========================================================================
__global__ __launch_bounds__(256) void im2col_split_kernel(
    const float* __restrict__ src,
    __nv_bfloat16* __restrict__ Shi, __nv_bfloat16* __restrict__ Slo)
{
    int p = blockIdx.x * 256 + threadIdx.x;   // grid.x = 32
    int k = blockIdx.y;                        // 27
    int c = blockIdx.z;                        // 256
    int z = p >> 10, y = (p >> 5) & 31, x = p & 31;
    int kd = k / 9, kh = (k / 3) % 3, kw = k % 3;
    int zz = z + kd - 1, yy = y + kh - 1, xx = x + kw - 1;
    float v = 0.0f;
    if ((unsigned)zz < DD && (unsigned)yy < HH && (unsigned)xx < WW)
        v = src[c * NSP + (zz << 10) + (yy << 5) + xx];
    __nv_bfloat16 hv = __float2bfloat16(v);
    size_t o = (size_t)(c * K27 + k) * NSP + p;
    Shi[o] = hv;
    Slo[o] = __float2bfloat16(v - __bfloat162float(hv));
}

// ===========================================================================
// Deformable sampling -> bf16 limb-split S  (S[(c*27+k)][p])
// ===========================================================================
__global__ void sample_kernel(const float* __restrict__ src,
                              const float* __restrict__ dd,
                              __nv_bfloat16* __restrict__ Shi,
                              __nv_bfloat16* __restrict__ Slo) {
    int p = blockIdx.x * 128 + threadIdx.x;   // grid.x = 64
    int k = blockIdx.y;                        // 27
    int z = p >> 10, y = (p >> 5) & 31, x = p & 31;
    int kd = k / 9, kh = (k / 3) % 3, kw = k % 3;

    float cd = (float)(z + kd - 1) + dd[(k * 3 + 0) * NSP + p];
    float ch = (float)(y + kh - 1) + dd[(k * 3 + 1) * NSP + p];
    float cw = (float)(x + kw - 1) + dd[(k * 3 + 2) * NSP + p];
    float m  = 1.0f / (1.0f + expf(-dd[(81 + k) * NSP + p]));

    float d0 = floorf(cd), h0 = floorf(ch), w0 = floorf(cw);
    float fd = cd - d0, fh = ch - h0, fw = cw - w0;
    int z0 = (int)d0, y0 = (int)h0, x0 = (int)w0;

    float wt[8]; int idx[8];
#pragma unroll
    for (int j = 0; j < 8; j++) {
        int dz = (j >> 2) & 1, dy = (j >> 1) & 1, dx = j & 1;
        int zi = z0 + dz, yi = y0 + dy, xi = x0 + dx;
        float w = (dz ? fd : 1.0f - fd) * (dy ? fh : 1.0f - fh) * (dx ? fw : 1.0f - fw);
        bool valid = ((unsigned)zi < DD) && ((unsigned)yi < HH) && ((unsigned)xi < WW);
        wt[j] = valid ? (w * m) : 0.0f;
        int zc = min(max(zi, 0), DD - 1);
        int yc = min(max(yi, 0), HH - 1);
        int xc = min(max(xi, 0), WW - 1);
        idx[j] = (zc << 10) + (yc << 5) + xc;
    }

    size_t base = (size_t)k * NSP + p;
#pragma unroll 4
    for (int c = 0; c < CIN; c++) {
        const float* b = src + c * NSP;
        float acc = wt[0] * b[idx[0]] + wt[1] * b[idx[1]]
                  + wt[2] * b[idx[2]] + wt[3] * b[idx[3]]
                  + wt[4] * b[idx[4]] + wt[5] * b[idx[5]]
                  + wt[6] * b[idx[6]] + wt[7] * b[idx[7]];
        __nv_bfloat16 hv = __float2bfloat16(acc);
        size_t o = base + (size_t)c * K27 * NSP;
        Shi[o] = hv;
        Slo[o] = __float2bfloat16(acc - __bfloat162float(hv));
    }
}

// ===========================================================================
// Tensor-core GEMM (mma.sync bf16, 2-limb split):
// C[z][M][8192] (+bias, +ReLU) = A[M][K] * S[K][8192], K-slice per blockIdx.z.
// CTA: 128(M) x 64(N), BK=32. 8 warps: wm = wid&3 (32 rows), wn = wid>>2.
// A rows padded to 40 bf16 (80B), B rows to 72 bf16 (144B): ldmatrix
// conflict-free. cp.async double-buffered.
// ===========================================================================
#define ASZ   (128 * 40 * 2)      // 10240 B per A limb tile
#define BSZ   (32 * 72 * 2)       // 4608 B per B limb tile
#define STAGE (2 * ASZ + 2 * BSZ) // 29696 B
#define SMTOT (2 * STAGE)         // 59392 B

__global__ __launch_bounds__(256) void mma_gemm(
    const __nv_bfloat16* __restrict__ Ahi, const __nv_bfloat16* __restrict__ Alo,
    const __nv_bfloat16* __restrict__ Bhi, const __nv_bfloat16* __restrict__ Blo,
    const float* __restrict__ bias, float* __restrict__ C,
    int M, int nkt, int doRelu, int zStride)
{
    extern __shared__ char smem[];
    uint32_t sb = smem_u32(smem);
    int tid = threadIdx.x;
    int wid = tid >> 5, lid = tid & 31;
    int p0 = blockIdx.x * 64;          // N tile base
    int mBase = blockIdx.y * 128;      // M tile base
    int ktBase = blockIdx.z * nkt;     // K-slice base (in BK=32 units)

    int wm = wid & 3;                  // 0..3 -> 32 rows each
    int wn = wid >> 2;                 // 0..1 -> 32 cols each
    int quad = lid >> 3, rr = lid & 7;

    // loader indices
    int aRow = tid >> 2;               // 0..63 (x2 with +64)
    int aU   = tid & 3;                // 16B unit in 64B row
    int bRow = tid >> 3;               // 0..31
    int bU   = tid & 7;                // 16B unit in 128B row

    float acc[2][4][4];
#pragma unroll
    for (int i = 0; i < 2; i++)
#pragma unroll
        for (int j = 0; j < 4; j++)
#pragma unroll
            for (int q = 0; q < 4; q++) acc[i][j][q] = 0.f;

    auto issue = [&](int buf, int kt) {
        uint32_t s = sb + buf * STAGE;
        int kOff = (ktBase + kt) * 32;
#pragma unroll
        for (int t = 0; t < 2; t++) {
            int row = aRow + t * 64;
            uint32_t d = s + row * 80 + aU * 16;
            const __nv_bfloat16* sh = Ahi + (size_t)(mBase + row) * CK + kOff + aU * 8;
            const __nv_bfloat16* sl = Alo + (size_t)(mBase + row) * CK + kOff + aU * 8;
            cp16(d, sh);
            cp16(d + ASZ, sl);
        }
        {
            uint32_t d = s + 2 * ASZ + bRow * 144 + bU * 16;
            const __nv_bfloat16* sh = Bhi + (size_t)(kOff + bRow) * NSP + p0 + bU * 8;
            const __nv_bfloat16* sl = Blo + (size_t)(kOff + bRow) * NSP + p0 + bU * 8;
            cp16(d, sh);
            cp16(d + BSZ, sl);
        }
        cp_commit();
    };

    issue(0, 0);

    for (int kt = 0; kt < nkt; kt++) {
        int buf = kt & 1;
        if (kt + 1 < nkt) {
            issue(buf ^ 1, kt + 1);
            cp_wait<1>();
        } else {
            cp_wait<0>();
        }
        __syncthreads();

        uint32_t s = sb + buf * STAGE;
#pragma unroll
        for (int ks = 0; ks < 2; ks++) {
            int k0 = ks * 16;
            uint32_t ah[2][4], al[2][4];
#pragma unroll
            for (int mf = 0; mf < 2; mf++) {
                int row = wm * 32 + mf * 16 + ((quad & 1) ? 8 : 0) + rr;
                int col = k0 + ((quad >> 1) ? 8 : 0);
                uint32_t ad = s + (uint32_t)(row * 40 + col) * 2;
                ldsm4(ah[mf], ad);
                ldsm4(al[mf], ad + ASZ);
            }
            uint32_t bh[8], bl[8];
#pragma unroll
            for (int nb = 0; nb < 2; nb++) {
                int row = k0 + ((quad & 1) ? 8 : 0) + rr;
                int col = wn * 32 + nb * 16 + ((quad >> 1) ? 8 : 0);
                uint32_t bd = s + 2 * ASZ + (uint32_t)(row * 72 + col) * 2;
                uint32_t t[4];
                ldsm4t(t, bd);
                bh[nb * 4 + 0] = t[0]; bh[nb * 4 + 1] = t[1];
                bh[nb * 4 + 2] = t[2]; bh[nb * 4 + 3] = t[3];
                ldsm4t(t, bd + BSZ);
                bl[nb * 4 + 0] = t[0]; bl[nb * 4 + 1] = t[1];
                bl[nb * 4 + 2] = t[2]; bl[nb * 4 + 3] = t[3];
            }
#pragma unroll
            for (int mf = 0; mf < 2; mf++) {
#pragma unroll
                for (int nf = 0; nf < 4; nf++) {
                    uint32_t b0h = bh[nf * 2], b1h = bh[nf * 2 + 1];
                    uint32_t b0l = bl[nf * 2], b1l = bl[nf * 2 + 1];
                    mma_bf16(acc[mf][nf], ah[mf], b0h, b1h);
                    mma_bf16(acc[mf][nf], al[mf], b0h, b1h);
                    mma_bf16(acc[mf][nf], ah[mf], b0l, b1l);
                }
            }
        }
        __syncthreads();
    }

    // epilogue: bias (+ReLU), fp32 stores, M-guarded
    float* Cz = C + (size_t)blockIdx.z * zStride;
    int g = lid >> 2, t4 = lid & 3;
#pragma unroll
    for (int mf = 0; mf < 2; mf++) {
        int row0 = mBase + wm * 32 + mf * 16 + g;
        int row1 = row0 + 8;
        float bv0 = (row0 < M) ? bias[row0] : 0.f;
        float bv1 = (row1 < M) ? bias[row1] : 0.f;
#pragma unroll
        for (int nf = 0; nf < 4; nf++) {
            int col = p0 + wn * 32 + nf * 8 + 2 * t4;
            float v0 = acc[mf][nf][0] + bv0;
            float v1 = acc[mf][nf][1] + bv0;
            float v2 = acc[mf][nf][2] + bv1;
            float v3 = acc[mf][nf][3] + bv1;
            if (doRelu) {
                v0 = fmaxf(v0, 0.f); v1 = fmaxf(v1, 0.f);
                v2 = fmaxf(v2, 0.f); v3 = fmaxf(v3, 0.f);
            }
            if (row0 < M) *(float2*)(Cz + (size_t)row0 * NSP + col) = make_float2(v0, v1);
            if (row1 < M) *(float2*)(Cz + (size_t)row1 * NSP + col) = make_float2(v2, v3);
        }
    }
}

// ===========================================================================
// Split-K combine (offset path): C = P0 + P1 + bias
// ===========================================================================
__global__ __launch_bounds__(256) void combine_kernel(
    const float* __restrict__ P0, const float* __restrict__ P1,
    const float* __restrict__ bias, float* __restrict__ C, int total4)
{
    int i = blockIdx.x * 256 + threadIdx.x;
    if (i >= total4) return;
    int row = i / (NSP / 4);
    float bv = bias[row];
    float4 a = ((const float4*)P0)[i];
    float4 b = ((const float4*)P1)[i];
    float4 r;
    r.x = a.x + b.x + bv; r.y = a.y + b.y + bv;
    r.z = a.z + b.z + bv; r.w = a.w + b.w + bv;
    ((float4*)C)[i] = r;
}

// ===========================================================================
// Driver
// ===========================================================================
extern "C" void kernel_launch(void* const* d_in, const int* in_sizes, int n_in,
                              void* d_out, int out_size) {
    (void)in_sizes; (void)n_in; (void)out_size;
    const float* x = (const float*)d_in[0];
    const float* ow[4] = { (const float*)d_in[1], (const float*)d_in[5],
                           (const float*)d_in[9], (const float*)d_in[13] };
    const float* ob[4] = { (const float*)d_in[2], (const float*)d_in[6],
                           (const float*)d_in[10], (const float*)d_in[14] };
    const float* w[4]  = { (const float*)d_in[3], (const float*)d_in[7],
                           (const float*)d_in[11], (const float*)d_in[15] };
    const float* b[4]  = { (const float*)d_in[4], (const float*)d_in[8],
                           (const float*)d_in[12], (const float*)d_in[16] };
    float* out = (float*)d_out;

    __nv_bfloat16 *Shi, *Slo, *Whi, *Wlo, *OWhi, *OWlo;
    float *dbuf, *hbuf, *dp, *zb;
    cudaGetSymbolAddress((void**)&Shi,  g_Shi);
    cudaGetSymbolAddress((void**)&Slo,  g_Slo);
    cudaGetSymbolAddress((void**)&Whi,  g_Whi);
    cudaGetSymbolAddress((void**)&Wlo,  g_Wlo);
    cudaGetSymbolAddress((void**)&OWhi, g_OWhi);
    cudaGetSymbolAddress((void**)&OWlo, g_OWlo);
    cudaGetSymbolAddress((void**)&dbuf, g_d);
    cudaGetSymbolAddress((void**)&hbuf, g_h);
    cudaGetSymbolAddress((void**)&dp,   g_dp);
    cudaGetSymbolAddress((void**)&zb,   g_zerobias);
    float* h0 = hbuf;
    float* h1 = hbuf + (size_t)CIN * NSP;

    static int smemSet = 0;
    if (!smemSet) {
        cudaFuncSetAttribute(mma_gemm, cudaFuncAttributeMaxDynamicSharedMemorySize, SMTOT);
        smemSet = 1;
    }

    dim3 im2colGrid(NSP / 256, K27, CIN);
    dim3 sampleGrid(NSP / 128, K27);
    dim3 offGrid(NSP / 64, 1, 2);            // 128 x 1 x splitK2 = 256 CTAs
    dim3 mainGrid(NSP / 64, 2, 1);           // 128 x 2 = 256 CTAs
    int wN = CIN * CK;
    int wBlocks  = (wN + 255) / 256;
    int owBlocks = (128 * CK + 255) / 256;
    int offTot4 = 108 * NSP / 4;
    int offCombBlocks = (offTot4 + 255) / 256;

    const float* in = x;
    for (int L = 0; L < 3; L++) {
        split_kernel<<<wBlocks, 256>>>(w[L], Whi, Wlo, wN);
        owsplit_kernel<<<owBlocks, 256>>>(ow[L], OWhi, OWlo);
        im2col_split_kernel<<<im2colGrid, 256>>>(in, Shi, Slo);
        mma_gemm<<<offGrid, 256, SMTOT>>>(OWhi, OWlo, Shi, Slo, zb, dp,
                                          108, 108, 0, 108 * NSP);
        combine_kernel<<<offCombBlocks, 256>>>(dp, dp + (size_t)108 * NSP,
                                               ob[L], dbuf, offTot4);
        sample_kernel<<<sampleGrid, 128>>>(in, dbuf, Shi, Slo);
        float* hn = (L & 1) ? h1 : h0;
        mma_gemm<<<mainGrid, 256, SMTOT>>>(Whi, Wlo, Shi, Slo, b[L], hn,
                                           256, 216, 1, 0);
        in = hn;
    }
    // final: offsets from conv(h3), deformable conv applied to ORIGINAL x, no ReLU
    split_kernel<<<wBlocks, 256>>>(w[3], Whi, Wlo, wN);
    owsplit_kernel<<<owBlocks, 256>>>(ow[3], OWhi, OWlo);
    im2col_split_kernel<<<im2colGrid, 256>>>(in, Shi, Slo);
    mma_gemm<<<offGrid, 256, SMTOT>>>(OWhi, OWlo, Shi, Slo, zb, dp,
                                      108, 108, 0, 108 * NSP);
    combine_kernel<<<offCombBlocks, 256>>>(dp, dp + (size_t)108 * NSP,
                                           ob[3], dbuf, offTot4);
    sample_kernel<<<sampleGrid, 128>>>(x, dbuf, Shi, Slo);
    mma_gemm<<<mainGrid, 256, SMTOT>>>(Whi, Wlo, Shi, Slo, b[3], out,
                                       256, 216, 0, 0);
}

// round 13
// speedup vs baseline: 1.9813x; 1.0279x over previous
#include <cuda_runtime.h>
#include <cuda_bf16.h>
#include <math.h>
#include <stdint.h>

// Problem constants
#define NSP   8192          // D*H*W = 8*32*32
#define CIN   256
#define K27   27
#define CK    6912          // CIN * 27
#define DD    8
#define HH    32
#define WW    32

typedef unsigned long long ull;

// Scratch (allocation-free rule: __device__ globals)
__device__ float g_d[108 * NSP];                    // offset-conv output
__device__ float g_h[2][CIN * NSP];                 // hidden ping-pong
__device__ float g_dp[2][108 * NSP];                // split-K partials (offset conv)
__device__ float g_zerobias[256];                   // zero bias for partial passes
__device__ __nv_bfloat16 g_Shi[(size_t)CK * NSP];   // im2col/sampled matrix hi limb
__device__ __nv_bfloat16 g_Slo[(size_t)CK * NSP];   // im2col/sampled matrix lo limb
__device__ __nv_bfloat16 g_Whi[(size_t)CIN * CK];   // main weights hi limb
__device__ __nv_bfloat16 g_Wlo[(size_t)CIN * CK];   // main weights lo limb
__device__ __nv_bfloat16 g_OWhi[(size_t)128 * CK];  // offset weights hi (padded to 128 rows)
__device__ __nv_bfloat16 g_OWlo[(size_t)128 * CK];  // offset weights lo

// ===========================================================================
// PTX helpers
// ===========================================================================
__device__ __forceinline__ uint32_t smem_u32(const void* p) {
    uint32_t a;
    asm("{ .reg .u64 t; cvta.to.shared.u64 t, %1; cvt.u32.u64 %0, t; }" : "=r"(a) : "l"(p));
    return a;
}
__device__ __forceinline__ void cp16(uint32_t dst, const void* src) {
    asm volatile("cp.async.cg.shared.global [%0], [%1], 16;" :: "r"(dst), "l"(src));
}
__device__ __forceinline__ void cp_commit() {
    asm volatile("cp.async.commit_group;" ::: "memory");
}
template <int N>
__device__ __forceinline__ void cp_wait() {
    asm volatile("cp.async.wait_group %0;" :: "n"(N) : "memory");
}
__device__ __forceinline__ void ldsm4(uint32_t* r, uint32_t addr) {
    asm volatile("ldmatrix.sync.aligned.m8n8.x4.shared.b16 {%0,%1,%2,%3}, [%4];"
                 : "=r"(r[0]), "=r"(r[1]), "=r"(r[2]), "=r"(r[3]) : "r"(addr));
}
__device__ __forceinline__ void ldsm4t(uint32_t* r, uint32_t addr) {
    asm volatile("ldmatrix.sync.aligned.m8n8.x4.trans.shared.b16 {%0,%1,%2,%3}, [%4];"
                 : "=r"(r[0]), "=r"(r[1]), "=r"(r[2]), "=r"(r[3]) : "r"(addr));
}
__device__ __forceinline__ void mma_bf16(float* d, const uint32_t* a, uint32_t b0, uint32_t b1) {
    asm volatile("mma.sync.aligned.m16n8k16.row.col.f32.bf16.bf16.f32 "
                 "{%0,%1,%2,%3}, {%4,%5,%6,%7}, {%8,%9}, {%0,%1,%2,%3};"
                 : "+f"(d[0]), "+f"(d[1]), "+f"(d[2]), "+f"(d[3])
                 : "r"(a[0]), "r"(a[1]), "r"(a[2]), "r"(a[3]), "r"(b0), "r"(b1));
}

// ===========================================================================
// Weight limb-split: fp32 -> (hi, lo) bf16
// ===========================================================================
__global__ __launch_bounds__(256) void split_kernel(
    const float* __restrict__ src, __nv_bfloat16* __restrict__ hi,
    __nv_bfloat16* __restrict__ lo, int n)
{
    int i = blockIdx.x * 256 + threadIdx.x;
    if (i >= n) return;
    float a = src[i];
    __nv_bfloat16 h = __float2bfloat16(a);
    hi[i] = h;
    lo[i] = __float2bfloat16(a - __bfloat162float(h));
}

// Padded variant: 128 rows, rows >= 108 are zero.
__global__ __launch_bounds__(256) void owsplit_kernel(
    const float* __restrict__ src, __nv_bfloat16* __restrict__ hi,
    __nv_bfloat16* __restrict__ lo)
{
    int i = blockIdx.x * 256 + threadIdx.x;
    if (i >= 128 * CK) return;
    int row = i / CK;
    float a = (row < 108) ? src[i] : 0.0f;
    __nv_bfloat16 h = __float2bfloat16(a);
    hi[i] = h;
    lo[i] = __float2bfloat16(a - __bfloat162float(h));
}

// ===========================================================================
// Fused im2col + limb split for the plain 3x3x3 pad-1 conv
// ===========================================================================
__global__ __launch_bounds__(256) void im2col_split_kernel(
    const float* __restrict__ src,
    __nv_bfloat16* __restrict__ Shi, __nv_bfloat16* __restrict__ Slo)
{
    int p = blockIdx.x * 256 + threadIdx.x;   // grid.x = 32
    int k = blockIdx.y;                        // 27
    int c = blockIdx.z;                        // 256
    int z = p >> 10, y = (p >> 5) & 31, x = p & 31;
    int kd = k / 9, kh = (k / 3) % 3, kw = k % 3;
    int zz = z + kd - 1, yy = y + kh - 1, xx = x + kw - 1;
    float v = 0.0f;
    if ((unsigned)zz < DD && (unsigned)yy < HH && (unsigned)xx < WW)
        v = src[c * NSP + (zz << 10) + (yy << 5) + xx];
    __nv_bfloat16 hv = __float2bfloat16(v);
    size_t o = (size_t)(c * K27 + k) * NSP + p;
    Shi[o] = hv;
    Slo[o] = __float2bfloat16(v - __bfloat162float(hv));
}

// ===========================================================================
// Deformable sampling -> bf16 limb-split S  (S[(c*27+k)][p])
// ===========================================================================
__global__ void sample_kernel(const float* __restrict__ src,
                              const float* __restrict__ dd,
                              __nv_bfloat16* __restrict__ Shi,
                              __nv_bfloat16* __restrict__ Slo) {
    int p = blockIdx.x * 128 + threadIdx.x;   // grid.x = 64
    int k = blockIdx.y;                        // 27
    int z = p >> 10, y = (p >> 5) & 31, x = p & 31;
    int kd = k / 9, kh = (k / 3) % 3, kw = k % 3;

    float cd = (float)(z + kd - 1) + dd[(k * 3 + 0) * NSP + p];
    float ch = (float)(y + kh - 1) + dd[(k * 3 + 1) * NSP + p];
    float cw = (float)(x + kw - 1) + dd[(k * 3 + 2) * NSP + p];
    float m  = 1.0f / (1.0f + expf(-dd[(81 + k) * NSP + p]));

    float d0 = floorf(cd), h0 = floorf(ch), w0 = floorf(cw);
    float fd = cd - d0, fh = ch - h0, fw = cw - w0;
    int z0 = (int)d0, y0 = (int)h0, x0 = (int)w0;

    float wt[8]; int idx[8];
#pragma unroll
    for (int j = 0; j < 8; j++) {
        int dz = (j >> 2) & 1, dy = (j >> 1) & 1, dx = j & 1;
        int zi = z0 + dz, yi = y0 + dy, xi = x0 + dx;
        float w = (dz ? fd : 1.0f - fd) * (dy ? fh : 1.0f - fh) * (dx ? fw : 1.0f - fw);
        bool valid = ((unsigned)zi < DD) && ((unsigned)yi < HH) && ((unsigned)xi < WW);
        wt[j] = valid ? (w * m) : 0.0f;
        int zc = min(max(zi, 0), DD - 1);
        int yc = min(max(yi, 0), HH - 1);
        int xc = min(max(xi, 0), WW - 1);
        idx[j] = (zc << 10) + (yc << 5) + xc;
    }

    size_t base = (size_t)k * NSP + p;
#pragma unroll 4
    for (int c = 0; c < CIN; c++) {
        const float* b = src + c * NSP;
        float acc = wt[0] * b[idx[0]] + wt[1] * b[idx[1]]
                  + wt[2] * b[idx[2]] + wt[3] * b[idx[3]]
                  + wt[4] * b[idx[4]] + wt[5] * b[idx[5]]
                  + wt[6] * b[idx[6]] + wt[7] * b[idx[7]];
        __nv_bfloat16 hv = __float2bfloat16(acc);
        size_t o = base + (size_t)c * K27 * NSP;
        Shi[o] = hv;
        Slo[o] = __float2bfloat16(acc - __bfloat162float(hv));
    }
}

// ===========================================================================
// Tensor-core GEMM (mma.sync bf16, 2-limb split), 3-stage cp.async pipeline:
// C[z][M][8192] (+bias, +ReLU) = A[M][K] * S[K][8192], K-slice per blockIdx.z.
// CTA: 128(M) x 64(N), BK=32. One __syncthreads per K-tile.
// ===========================================================================
#define ASZ   (128 * 40 * 2)      // 10240 B per A limb tile
#define BSZ   (32 * 72 * 2)       // 4608 B per B limb tile
#define STAGE (2 * ASZ + 2 * BSZ) // 29696 B
#define NSTAGE 3
#define SMTOT (NSTAGE * STAGE)    // 89088 B

__global__ __launch_bounds__(256) void mma_gemm(
    const __nv_bfloat16* __restrict__ Ahi, const __nv_bfloat16* __restrict__ Alo,
    const __nv_bfloat16* __restrict__ Bhi, const __nv_bfloat16* __restrict__ Blo,
    const float* __restrict__ bias, float* __restrict__ C,
    int M, int nkt, int doRelu, int zStride)
{
    extern __shared__ char smem[];
    uint32_t sb = smem_u32(smem);
    int tid = threadIdx.x;
    int wid = tid >> 5, lid = tid & 31;
    int p0 = blockIdx.x * 64;          // N tile base
    int mBase = blockIdx.y * 128;      // M tile base
    int ktBase = blockIdx.z * nkt;     // K-slice base (in BK=32 units)

    int wm = wid & 3;                  // 0..3 -> 32 rows each
    int wn = wid >> 2;                 // 0..1 -> 32 cols each
    int quad = lid >> 3, rr = lid & 7;

    // loader indices
    int aRow = tid >> 2;               // 0..63 (x2 with +64)
    int aU   = tid & 3;                // 16B unit in 64B row
    int bRow = tid >> 3;               // 0..31
    int bU   = tid & 7;                // 16B unit in 128B row

    float acc[2][4][4];
#pragma unroll
    for (int i = 0; i < 2; i++)
#pragma unroll
        for (int j = 0; j < 4; j++)
#pragma unroll
            for (int q = 0; q < 4; q++) acc[i][j][q] = 0.f;

    auto issue = [&](int st, int kt) {
        uint32_t s = sb + st * STAGE;
        int kOff = (ktBase + kt) * 32;
#pragma unroll
        for (int t = 0; t < 2; t++) {
            int row = aRow + t * 64;
            uint32_t d = s + row * 80 + aU * 16;
            const __nv_bfloat16* sh = Ahi + (size_t)(mBase + row) * CK + kOff + aU * 8;
            const __nv_bfloat16* sl = Alo + (size_t)(mBase + row) * CK + kOff + aU * 8;
            cp16(d, sh);
            cp16(d + ASZ, sl);
        }
        {
            uint32_t d = s + 2 * ASZ + bRow * 144 + bU * 16;
            const __nv_bfloat16* sh = Bhi + (size_t)(kOff + bRow) * NSP + p0 + bU * 8;
            const __nv_bfloat16* sl = Blo + (size_t)(kOff + bRow) * NSP + p0 + bU * 8;
            cp16(d, sh);
            cp16(d + BSZ, sl);
        }
        cp_commit();
    };

    // preload stages 0 and 1
    issue(0, 0);
    if (nkt > 1) issue(1, 1);

    int st = 0;
    for (int kt = 0; kt < nkt; kt++) {
        cp_wait<1>();          // stage for kt has landed (per-thread groups)
        __syncthreads();       // publish stage kt; separate prior compute from new issue

        if (kt + 2 < nkt) {
            int nst = st + 2; if (nst >= NSTAGE) nst -= NSTAGE;
            issue(nst, kt + 2);    // writes the stage freed at iteration kt-1
        }

        uint32_t s = sb + st * STAGE;
#pragma unroll
        for (int ks = 0; ks < 2; ks++) {
            int k0 = ks * 16;
            uint32_t ah[2][4], al[2][4];
#pragma unroll
            for (int mf = 0; mf < 2; mf++) {
                int row = wm * 32 + mf * 16 + ((quad & 1) ? 8 : 0) + rr;
                int col = k0 + ((quad >> 1) ? 8 : 0);
                uint32_t ad = s + (uint32_t)(row * 40 + col) * 2;
                ldsm4(ah[mf], ad);
                ldsm4(al[mf], ad + ASZ);
            }
            uint32_t bh[8], bl[8];
#pragma unroll
            for (int nb = 0; nb < 2; nb++) {
                int row = k0 + ((quad & 1) ? 8 : 0) + rr;
                int col = wn * 32 + nb * 16 + ((quad >> 1) ? 8 : 0);
                uint32_t bd = s + 2 * ASZ + (uint32_t)(row * 72 + col) * 2;
                uint32_t t[4];
                ldsm4t(t, bd);
                bh[nb * 4 + 0] = t[0]; bh[nb * 4 + 1] = t[1];
                bh[nb * 4 + 2] = t[2]; bh[nb * 4 + 3] = t[3];
                ldsm4t(t, bd + BSZ);
                bl[nb * 4 + 0] = t[0]; bl[nb * 4 + 1] = t[1];
                bl[nb * 4 + 2] = t[2]; bl[nb * 4 + 3] = t[3];
            }
#pragma unroll
            for (int mf = 0; mf < 2; mf++) {
#pragma unroll
                for (int nf = 0; nf < 4; nf++) {
                    uint32_t b0h = bh[nf * 2], b1h = bh[nf * 2 + 1];
                    uint32_t b0l = bl[nf * 2], b1l = bl[nf * 2 + 1];
                    mma_bf16(acc[mf][nf], ah[mf], b0h, b1h);
                    mma_bf16(acc[mf][nf], al[mf], b0h, b1h);
                    mma_bf16(acc[mf][nf], ah[mf], b0l, b1l);
                }
            }
        }
        st++; if (st >= NSTAGE) st = 0;
    }

    // epilogue: bias (+ReLU), fp32 stores, M-guarded
    float* Cz = C + (size_t)blockIdx.z * zStride;
    int g = lid >> 2, t4 = lid & 3;
#pragma unroll
    for (int mf = 0; mf < 2; mf++) {
        int row0 = mBase + wm * 32 + mf * 16 + g;
        int row1 = row0 + 8;
        float bv0 = (row0 < M) ? bias[row0] : 0.f;
        float bv1 = (row1 < M) ? bias[row1] : 0.f;
#pragma unroll
        for (int nf = 0; nf < 4; nf++) {
            int col = p0 + wn * 32 + nf * 8 + 2 * t4;
            float v0 = acc[mf][nf][0] + bv0;
            float v1 = acc[mf][nf][1] + bv0;
            float v2 = acc[mf][nf][2] + bv1;
            float v3 = acc[mf][nf][3] + bv1;
            if (doRelu) {
                v0 = fmaxf(v0, 0.f); v1 = fmaxf(v1, 0.f);
                v2 = fmaxf(v2, 0.f); v3 = fmaxf(v3, 0.f);
            }
            if (row0 < M) *(float2*)(Cz + (size_t)row0 * NSP + col) = make_float2(v0, v1);
            if (row1 < M) *(float2*)(Cz + (size_t)row1 * NSP + col) = make_float2(v2, v3);
        }
    }
}

// ===========================================================================
// Split-K combine (offset path): C = P0 + P1 + bias
// ===========================================================================
__global__ __launch_bounds__(256) void combine_kernel(
    const float* __restrict__ P0, const float* __restrict__ P1,
    const float* __restrict__ bias, float* __restrict__ C, int total4)
{
    int i = blockIdx.x * 256 + threadIdx.x;
    if (i >= total4) return;
    int row = i / (NSP / 4);
    float bv = bias[row];
    float4 a = ((const float4*)P0)[i];
    float4 b = ((const float4*)P1)[i];
    float4 r;
    r.x = a.x + b.x + bv; r.y = a.y + b.y + bv;
    r.z = a.z + b.z + bv; r.w = a.w + b.w + bv;
    ((float4*)C)[i] = r;
}

// ===========================================================================
// Driver
// ===========================================================================
extern "C" void kernel_launch(void* const* d_in, const int* in_sizes, int n_in,
                              void* d_out, int out_size) {
    (void)in_sizes; (void)n_in; (void)out_size;
    const float* x = (const float*)d_in[0];
    const float* ow[4] = { (const float*)d_in[1], (const float*)d_in[5],
                           (const float*)d_in[9], (const float*)d_in[13] };
    const float* ob[4] = { (const float*)d_in[2], (const float*)d_in[6],
                           (const float*)d_in[10], (const float*)d_in[14] };
    const float* w[4]  = { (const float*)d_in[3], (const float*)d_in[7],
                           (const float*)d_in[11], (const float*)d_in[15] };
    const float* b[4]  = { (const float*)d_in[4], (const float*)d_in[8],
                           (const float*)d_in[12], (const float*)d_in[16] };
    float* out = (float*)d_out;

    __nv_bfloat16 *Shi, *Slo, *Whi, *Wlo, *OWhi, *OWlo;
    float *dbuf, *hbuf, *dp, *zb;
    cudaGetSymbolAddress((void**)&Shi,  g_Shi);
    cudaGetSymbolAddress((void**)&Slo,  g_Slo);
    cudaGetSymbolAddress((void**)&Whi,  g_Whi);
    cudaGetSymbolAddress((void**)&Wlo,  g_Wlo);
    cudaGetSymbolAddress((void**)&OWhi, g_OWhi);
    cudaGetSymbolAddress((void**)&OWlo, g_OWlo);
    cudaGetSymbolAddress((void**)&dbuf, g_d);
    cudaGetSymbolAddress((void**)&hbuf, g_h);
    cudaGetSymbolAddress((void**)&dp,   g_dp);
    cudaGetSymbolAddress((void**)&zb,   g_zerobias);
    float* h0 = hbuf;
    float* h1 = hbuf + (size_t)CIN * NSP;

    static int smemSet = 0;
    if (!smemSet) {
        cudaFuncSetAttribute(mma_gemm, cudaFuncAttributeMaxDynamicSharedMemorySize, SMTOT);
        smemSet = 1;
    }

    dim3 im2colGrid(NSP / 256, K27, CIN);
    dim3 sampleGrid(NSP / 128, K27);
    dim3 offGrid(NSP / 64, 1, 2);            // 128 x 1 x splitK2 = 256 CTAs
    dim3 mainGrid(NSP / 64, 2, 1);           // 128 x 2 = 256 CTAs
    int wN = CIN * CK;
    int wBlocks  = (wN + 255) / 256;
    int owBlocks = (128 * CK + 255) / 256;
    int offTot4 = 108 * NSP / 4;
    int offCombBlocks = (offTot4 + 255) / 256;

    const float* in = x;
    for (int L = 0; L < 3; L++) {
        split_kernel<<<wBlocks, 256>>>(w[L], Whi, Wlo, wN);
        owsplit_kernel<<<owBlocks, 256>>>(ow[L], OWhi, OWlo);
        im2col_split_kernel<<<im2colGrid, 256>>>(in, Shi, Slo);
        mma_gemm<<<offGrid, 256, SMTOT>>>(OWhi, OWlo, Shi, Slo, zb, dp,
                                          108, 108, 0, 108 * NSP);
        combine_kernel<<<offCombBlocks, 256>>>(dp, dp + (size_t)108 * NSP,
                                               ob[L], dbuf, offTot4);
        sample_kernel<<<sampleGrid, 128>>>(in, dbuf, Shi, Slo);
        float* hn = (L & 1) ? h1 : h0;
        mma_gemm<<<mainGrid, 256, SMTOT>>>(Whi, Wlo, Shi, Slo, b[L], hn,
                                           256, 216, 1, 0);
        in = hn;
    }
    // final: offsets from conv(h3), deformable conv applied to ORIGINAL x, no ReLU
    split_kernel<<<wBlocks, 256>>>(w[3], Whi, Wlo, wN);
    owsplit_kernel<<<owBlocks, 256>>>(ow[3], OWhi, OWlo);
    im2col_split_kernel<<<im2colGrid, 256>>>(in, Shi, Slo);
    mma_gemm<<<offGrid, 256, SMTOT>>>(OWhi, OWlo, Shi, Slo, zb, dp,
                                      108, 108, 0, 108 * NSP);
    combine_kernel<<<offCombBlocks, 256>>>(dp, dp + (size_t)108 * NSP,
                                           ob[3], dbuf, offTot4);
    sample_kernel<<<sampleGrid, 128>>>(x, dbuf, Shi, Slo);
    mma_gemm<<<mainGrid, 256, SMTOT>>>(Whi, Wlo, Shi, Slo, b[3], out,
                                       256, 216, 0, 0);
}